// round 5
// baseline (speedup 1.0000x reference)
#include <cuda_runtime.h>
#include <math.h>
#include <stdint.h>

#define NTOK 65536            // 16 * 4096
#define DIM 256
#define QKVC 768
#define HID 1024

// ---------------- scratch ----------------------------------------------------
__device__ float g_ln  [(size_t)NTOK * DIM];
__device__ float g_qkv [(size_t)NTOK * QKVC];
__device__ float g_attn[(size_t)NTOK * DIM];
__device__ float g_mlp [(size_t)NTOK * HID];
#define WT_QKV 0
#define WT_PROJ (QKVC * DIM)
#define WT_FC1  (WT_PROJ + DIM * DIM)
#define WT_FC2  (WT_FC1 + HID * DIM)
__device__ float g_wt[WT_FC2 + DIM * HID];

// ---------------- helpers -----------------------------------------------------
__device__ __forceinline__ uint32_t smem_u32(const void* p) {
    return (uint32_t)__cvta_generic_to_shared((void*)p);
}
__device__ __forceinline__ void cp_async16(uint32_t dst, const void* src) {
    asm volatile("cp.async.cg.shared.global [%0], [%1], 16;" :: "r"(dst), "l"(src));
}
__device__ __forceinline__ float gelu_exact(float v) {
    return 0.5f * v * (1.0f + erff(v * 0.70710678118654752f));
}
__device__ __forceinline__ void mma_tf32(float* c, const uint32_t* a, const uint32_t* b) {
    asm volatile(
        "mma.sync.aligned.m16n8k8.row.col.f32.tf32.tf32.f32 "
        "{%0,%1,%2,%3}, {%4,%5,%6,%7}, {%8,%9}, {%0,%1,%2,%3};"
        : "+f"(c[0]), "+f"(c[1]), "+f"(c[2]), "+f"(c[3])
        : "r"(a[0]), "r"(a[1]), "r"(a[2]), "r"(a[3]), "r"(b[0]), "r"(b[1]));
}

// ---------------- transpose [R][C] -> [C][R] ---------------------------------
__global__ void transpose_kernel(const float* __restrict__ in, float* __restrict__ out,
                                 int R, int C) {
    __shared__ float t[32][33];
    int bx = blockIdx.x * 32, by = blockIdx.y * 32;
    int x = threadIdx.x, y = threadIdx.y;
    #pragma unroll
    for (int j = 0; j < 32; j += 8)
        t[y + j][x] = in[(size_t)(by + y + j) * C + bx + x];
    __syncthreads();
    #pragma unroll
    for (int j = 0; j < 32; j += 8)
        out[(size_t)(bx + y + j) * R + by + x] = t[x][y + j];
}

// ---------------- LayerNorm: one warp per token (C=256) ----------------------
__global__ void ln_kernel(const float* __restrict__ x,
                          const float* __restrict__ g,
                          const float* __restrict__ b,
                          float* __restrict__ out) {
    int warp = (blockIdx.x * blockDim.x + threadIdx.x) >> 5;
    int lane = threadIdx.x & 31;
    if (warp >= NTOK) return;
    const float* xp = x + (size_t)warp * DIM;
    float4 v0 = *(const float4*)(xp + lane * 4);
    float4 v1 = *(const float4*)(xp + 128 + lane * 4);
    float s  = v0.x + v0.y + v0.z + v0.w + v1.x + v1.y + v1.z + v1.w;
    float ss = v0.x*v0.x + v0.y*v0.y + v0.z*v0.z + v0.w*v0.w
             + v1.x*v1.x + v1.y*v1.y + v1.z*v1.z + v1.w*v1.w;
    #pragma unroll
    for (int o = 16; o > 0; o >>= 1) {
        s  += __shfl_xor_sync(0xffffffffu, s,  o);
        ss += __shfl_xor_sync(0xffffffffu, ss, o);
    }
    float mu  = s * (1.0f / DIM);
    float var = ss * (1.0f / DIM) - mu * mu;
    float inv = rsqrtf(var + 1e-5f);
    float4 g0 = *(const float4*)(g + lane * 4);
    float4 g1 = *(const float4*)(g + 128 + lane * 4);
    float4 b0 = *(const float4*)(b + lane * 4);
    float4 b1 = *(const float4*)(b + 128 + lane * 4);
    float4 o0, o1;
    o0.x = (v0.x - mu) * inv * g0.x + b0.x;
    o0.y = (v0.y - mu) * inv * g0.y + b0.y;
    o0.z = (v0.z - mu) * inv * g0.z + b0.z;
    o0.w = (v0.w - mu) * inv * g0.w + b0.w;
    o1.x = (v1.x - mu) * inv * g1.x + b1.x;
    o1.y = (v1.y - mu) * inv * g1.y + b1.y;
    o1.z = (v1.z - mu) * inv * g1.z + b1.z;
    o1.w = (v1.w - mu) * inv * g1.w + b1.w;
    float* op = out + (size_t)warp * DIM;
    *(float4*)(op + lane * 4)       = o0;
    *(float4*)(op + 128 + lane * 4) = o1;
}

// ---------------- tf32 mma.sync GEMM, block 128(M) x 256(N), 512 threads -----
// 16 warps: 4(M) x 4(N), warp tile 32x64 = 2x8 m16n8k8 atoms.
#define ASTRIDE 36
#define STAGE_A_F (128 * ASTRIDE)
#define STAGE_B_F (256 * ASTRIDE)
#define STAGE_F   (STAGE_A_F + STAGE_B_F)
#define GSM_TOTAL (2 * STAGE_F * 4)       // 110592 bytes

template<int EPI>
__global__ __launch_bounds__(512, 1)
void tc_gemm(const float* __restrict__ A, const float* __restrict__ Bt,
             float* __restrict__ C, int K, int N,
             const float* __restrict__ bias, const float* __restrict__ res) {
    extern __shared__ float sm[];
    // per stage: [A: 128*36][B: 256*36]
    int tid = threadIdx.x;
    int lane = tid & 31, wid = tid >> 5;
    int warp_m = wid & 3;        // 0..3
    int warp_n = wid >> 2;       // 0..3
    int block_row = blockIdx.y * 128;
    int block_col = blockIdx.x * 256;

    const float* gA = A  + (size_t)block_row * K;
    const float* gB = Bt + (size_t)block_col * K;

    uint32_t smA_u[2], smB_u[2];
    smA_u[0] = smem_u32(sm);
    smB_u[0] = smem_u32(sm + STAGE_A_F);
    smA_u[1] = smem_u32(sm + STAGE_F);
    smB_u[1] = smem_u32(sm + STAGE_F + STAGE_A_F);

    auto stage = [&](int c, int s) {
        int c0 = c * 32;
        #pragma unroll
        for (int it = 0; it < 2; ++it) {
            int seg = tid + it * 512;           // 0..1023
            int r = seg >> 3, c4 = (seg & 7) * 4;
            cp_async16(smA_u[s] + (uint32_t)(r * ASTRIDE + c4) * 4,
                       gA + (size_t)r * K + c0 + c4);
        }
        #pragma unroll
        for (int it = 0; it < 4; ++it) {
            int seg = tid + it * 512;           // 0..2047
            int r = seg >> 3, c4 = (seg & 7) * 4;
            cp_async16(smB_u[s] + (uint32_t)(r * ASTRIDE + c4) * 4,
                       gB + (size_t)r * K + c0 + c4);
        }
        asm volatile("cp.async.commit_group;");
    };

    float acc[2][8][4];
    #pragma unroll
    for (int i = 0; i < 2; i++)
        #pragma unroll
        for (int j = 0; j < 8; j++)
            #pragma unroll
            for (int q = 0; q < 4; q++) acc[i][j][q] = 0.0f;

    const int nch = K >> 5;
    stage(0, 0);

    int a_base = (warp_m * 32 + (lane >> 2)) * ASTRIDE + (lane & 3);
    int b_base = (warp_n * 64 + (lane >> 2)) * ASTRIDE + (lane & 3);

    for (int c = 0; c < nch; ++c) {
        int s = c & 1;
        if (c + 1 < nch) {
            stage(c + 1, s ^ 1);
            asm volatile("cp.async.wait_group 1;");
        } else {
            asm volatile("cp.async.wait_group 0;");
        }
        __syncthreads();
        const uint32_t* As = (const uint32_t*)(sm + (size_t)s * STAGE_F);
        const uint32_t* Bs = As + STAGE_A_F;
        #pragma unroll
        for (int kk = 0; kk < 32; kk += 8) {
            uint32_t a[2][4];
            #pragma unroll
            for (int am = 0; am < 2; ++am) {
                int base = a_base + am * 16 * ASTRIDE + kk;
                a[am][0] = As[base];
                a[am][1] = As[base + 8 * ASTRIDE];
                a[am][2] = As[base + 4];
                a[am][3] = As[base + 8 * ASTRIDE + 4];
            }
            uint32_t b[8][2];
            #pragma unroll
            for (int bn = 0; bn < 8; ++bn) {
                int base = b_base + bn * 8 * ASTRIDE + kk;
                b[bn][0] = Bs[base];
                b[bn][1] = Bs[base + 4];
            }
            #pragma unroll
            for (int am = 0; am < 2; ++am)
                #pragma unroll
                for (int bn = 0; bn < 8; ++bn)
                    mma_tf32(acc[am][bn], a[am], b[bn]);
        }
        __syncthreads();
    }

    #pragma unroll
    for (int am = 0; am < 2; ++am) {
        int row0 = block_row + warp_m * 32 + am * 16 + (lane >> 2);
        #pragma unroll
        for (int bn = 0; bn < 8; ++bn) {
            int col = block_col + warp_n * 64 + bn * 8 + 2 * (lane & 3);
            float2 v0 = make_float2(acc[am][bn][0], acc[am][bn][1]);
            float2 v1 = make_float2(acc[am][bn][2], acc[am][bn][3]);
            if (EPI >= 1) {
                float bx = bias[col], by = bias[col + 1];
                v0.x += bx; v0.y += by; v1.x += bx; v1.y += by;
            }
            if (EPI == 2) {
                v0.x = gelu_exact(v0.x); v0.y = gelu_exact(v0.y);
                v1.x = gelu_exact(v1.x); v1.y = gelu_exact(v1.y);
            }
            if (EPI == 3) {
                const float2 r0 = *(const float2*)&res[(size_t)row0 * N + col];
                const float2 r1 = *(const float2*)&res[(size_t)(row0 + 8) * N + col];
                v0.x += r0.x; v0.y += r0.y; v1.x += r1.x; v1.y += r1.y;
            }
            *(float2*)&C[(size_t)row0 * N + col]       = v0;
            *(float2*)&C[(size_t)(row0 + 8) * N + col] = v1;
        }
    }
}

// ---------------- windowed attention ------------------------------------------
__global__ __launch_bounds__(64) void attn_kernel(
    const float* __restrict__ qkv,
    const float* __restrict__ relb,
    float* __restrict__ out) {
    int wi = blockIdx.x;
    int h  = blockIdx.y;
    int n  = threadIdx.x;

    __shared__ float sq[64][36];
    __shared__ float sk[64][36];
    __shared__ float sv[64][36];

    int b = wi >> 6, wrem = wi & 63;
    int wh = wrem >> 3, ww = wrem & 7;
    int tok_row = b * 4096 + wh * 8 * 64 + ww * 8;

    {
        int f4 = (n & 7) * 4;
        int tsub = n >> 3;
        #pragma unroll
        for (int it = 0; it < 8; ++it) {
            int t = it * 8 + tsub;
            int ih = t >> 3, iw = t & 7;
            int gt = tok_row + ih * 64 + iw;
            const float* base = qkv + (size_t)gt * QKVC + h * 32 + f4;
            float4 tq = *(const float4*)(base);
            float4 tk = *(const float4*)(base + 256);
            float4 tv = *(const float4*)(base + 512);
            *(float4*)&sq[t][f4] = tq;
            *(float4*)&sk[t][f4] = tk;
            *(float4*)&sv[t][f4] = tv;
        }
    }
    __syncthreads();

    const float scale = 0.17677669529663688f;
    float q[32];
    #pragma unroll
    for (int i = 0; i < 8; i++) {
        float4 v = *(const float4*)&sq[n][4 * i];
        q[4*i+0] = v.x * scale; q[4*i+1] = v.y * scale;
        q[4*i+2] = v.z * scale; q[4*i+3] = v.w * scale;
    }

    int ih = n >> 3, iw = n & 7;
    float mx = -1e30f, sum = 0.0f;
    float o[32];
    #pragma unroll
    for (int d = 0; d < 32; d++) o[d] = 0.0f;

    #pragma unroll 2
    for (int m = 0; m < 64; m++) {
        int jh = m >> 3, jw = m & 7;
        int ridx = (ih - jh + 7) * 15 + (iw - jw + 7);
        float sc = __ldg(&relb[ridx * 8 + h]);
        #pragma unroll
        for (int i = 0; i < 8; i++) {
            float4 kv = *(const float4*)&sk[m][4 * i];
            sc = fmaf(q[4*i+0], kv.x, sc);
            sc = fmaf(q[4*i+1], kv.y, sc);
            sc = fmaf(q[4*i+2], kv.z, sc);
            sc = fmaf(q[4*i+3], kv.w, sc);
        }
        float nm = fmaxf(mx, sc);
        float corr = __expf(mx - nm);
        float p = __expf(sc - nm);
        sum = sum * corr + p;
        #pragma unroll
        for (int i = 0; i < 8; i++) {
            float4 vv = *(const float4*)&sv[m][4 * i];
            o[4*i+0] = fmaf(o[4*i+0], corr, p * vv.x);
            o[4*i+1] = fmaf(o[4*i+1], corr, p * vv.y);
            o[4*i+2] = fmaf(o[4*i+2], corr, p * vv.z);
            o[4*i+3] = fmaf(o[4*i+3], corr, p * vv.w);
        }
        mx = nm;
    }
    float inv = 1.0f / sum;
    #pragma unroll
    for (int i = 0; i < 8; i++) {
        float4 v = make_float4(o[4*i] * inv, o[4*i+1] * inv, o[4*i+2] * inv, o[4*i+3] * inv);
        *(float4*)&sq[n][4 * i] = v;
    }
    __syncthreads();
    {
        int f4 = (n & 7) * 4;
        int tsub = n >> 3;
        #pragma unroll
        for (int it = 0; it < 8; ++it) {
            int t = it * 8 + tsub;
            int th = t >> 3, tw = t & 7;
            int gt = tok_row + th * 64 + tw;
            *(float4*)(out + (size_t)gt * DIM + h * 32 + f4) = *(const float4*)&sq[t][f4];
        }
    }
}

// ---------------- launch ------------------------------------------------------
extern "C" void kernel_launch(void* const* d_in, const int* in_sizes, int n_in,
                              void* d_out, int out_size) {
    const float* x      = (const float*)d_in[0];
    const float* ln1_g  = (const float*)d_in[3];
    const float* ln1_b  = (const float*)d_in[4];
    const float* qkv_w  = (const float*)d_in[5];
    const float* proj_w = (const float*)d_in[6];
    const float* proj_b = (const float*)d_in[7];
    const float* relb   = (const float*)d_in[8];
    const float* ln2_g  = (const float*)d_in[9];
    const float* ln2_b  = (const float*)d_in[10];
    const float* fc1_w  = (const float*)d_in[11];
    const float* fc1_b  = (const float*)d_in[12];
    const float* fc2_w  = (const float*)d_in[13];
    const float* fc2_b  = (const float*)d_in[14];
    float* out = (float*)d_out;

    float *p_ln, *p_qkv, *p_attn, *p_mlp, *p_wt;
    cudaGetSymbolAddress((void**)&p_ln,   g_ln);
    cudaGetSymbolAddress((void**)&p_qkv,  g_qkv);
    cudaGetSymbolAddress((void**)&p_attn, g_attn);
    cudaGetSymbolAddress((void**)&p_mlp,  g_mlp);
    cudaGetSymbolAddress((void**)&p_wt,   g_wt);

    cudaFuncSetAttribute(tc_gemm<0>, cudaFuncAttributeMaxDynamicSharedMemorySize, GSM_TOTAL);
    cudaFuncSetAttribute(tc_gemm<2>, cudaFuncAttributeMaxDynamicSharedMemorySize, GSM_TOTAL);
    cudaFuncSetAttribute(tc_gemm<3>, cudaFuncAttributeMaxDynamicSharedMemorySize, GSM_TOTAL);

    transpose_kernel<<<dim3(QKVC / 32, DIM / 32), dim3(32, 8)>>>(qkv_w, p_wt + WT_QKV, DIM, QKVC);
    transpose_kernel<<<dim3(DIM / 32, DIM / 32),  dim3(32, 8)>>>(proj_w, p_wt + WT_PROJ, DIM, DIM);
    transpose_kernel<<<dim3(HID / 32, DIM / 32),  dim3(32, 8)>>>(fc1_w, p_wt + WT_FC1, DIM, HID);
    transpose_kernel<<<dim3(DIM / 32, HID / 32),  dim3(32, 8)>>>(fc2_w, p_wt + WT_FC2, HID, DIM);

    ln_kernel<<<NTOK / 8, 256>>>(x, ln1_g, ln1_b, p_ln);
    tc_gemm<0><<<dim3(QKVC / 256, NTOK / 128), 512, GSM_TOTAL>>>(
        p_ln, p_wt + WT_QKV, p_qkv, DIM, QKVC, nullptr, nullptr);
    attn_kernel<<<dim3(1024, 8), 64>>>(p_qkv, relb, p_attn);
    tc_gemm<3><<<dim3(DIM / 256, NTOK / 128), 512, GSM_TOTAL>>>(
        p_attn, p_wt + WT_PROJ, out, DIM, DIM, proj_b, x);
    ln_kernel<<<NTOK / 8, 256>>>(out, ln2_g, ln2_b, p_ln);
    tc_gemm<2><<<dim3(HID / 256, NTOK / 128), 512, GSM_TOTAL>>>(
        p_ln, p_wt + WT_FC1, p_mlp, DIM, HID, fc1_b, nullptr);
    tc_gemm<3><<<dim3(DIM / 256, NTOK / 128), 512, GSM_TOTAL>>>(
        p_mlp, p_wt + WT_FC2, out, HID, DIM, fc2_b, out);
}

// round 6
// speedup vs baseline: 1.4569x; 1.4569x over previous
#include <cuda_runtime.h>
#include <cuda_fp16.h>
#include <math.h>
#include <stdint.h>

#define NTOK 65536            // 16 * 4096
#define DIM 256
#define QKVC 768
#define HID 1024

// ---------------- scratch ----------------------------------------------------
__device__ __half g_lnh  [(size_t)NTOK * DIM];   // LN output (half)
__device__ float  g_qkv  [(size_t)NTOK * QKVC];  // qkv projection (fp32)
__device__ __half g_attnh[(size_t)NTOK * DIM];   // attention output (half)
__device__ __half g_mlph [(size_t)NTOK * HID];   // fc1+gelu output (half)
#define WT_QKV 0
#define WT_PROJ (QKVC * DIM)
#define WT_FC1  (WT_PROJ + DIM * DIM)
#define WT_FC2  (WT_FC1 + HID * DIM)
__device__ __half g_wth[WT_FC2 + DIM * HID];     // transposed half weights

// ---------------- helpers -----------------------------------------------------
__device__ __forceinline__ uint32_t smem_u32(const void* p) {
    return (uint32_t)__cvta_generic_to_shared((void*)p);
}
__device__ __forceinline__ void cp_async16(uint32_t dst, const void* src) {
    asm volatile("cp.async.cg.shared.global [%0], [%1], 16;" :: "r"(dst), "l"(src));
}
__device__ __forceinline__ float gelu_exact(float v) {
    return 0.5f * v * (1.0f + erff(v * 0.70710678118654752f));
}
__device__ __forceinline__ void mma_f16(float* c, const uint32_t* a, const uint32_t* b) {
    asm volatile(
        "mma.sync.aligned.m16n8k16.row.col.f32.f16.f16.f32 "
        "{%0,%1,%2,%3}, {%4,%5,%6,%7}, {%8,%9}, {%0,%1,%2,%3};"
        : "+f"(c[0]), "+f"(c[1]), "+f"(c[2]), "+f"(c[3])
        : "r"(a[0]), "r"(a[1]), "r"(a[2]), "r"(a[3]), "r"(b[0]), "r"(b[1]));
}

// ---------------- transpose+convert [R][C] f32 -> [C][R] f16 ------------------
__global__ void transpose_h_kernel(const float* __restrict__ in, __half* __restrict__ out,
                                   int R, int C) {
    __shared__ float t[32][33];
    int bx = blockIdx.x * 32, by = blockIdx.y * 32;
    int x = threadIdx.x, y = threadIdx.y;
    #pragma unroll
    for (int j = 0; j < 32; j += 8)
        t[y + j][x] = in[(size_t)(by + y + j) * C + bx + x];
    __syncthreads();
    #pragma unroll
    for (int j = 0; j < 32; j += 8)
        out[(size_t)(bx + y + j) * R + by + x] = __float2half(t[x][y + j]);
}

// ---------------- LayerNorm: one warp per token, fp32 in -> fp16 out ----------
__global__ void ln_kernel(const float* __restrict__ x,
                          const float* __restrict__ g,
                          const float* __restrict__ b,
                          __half* __restrict__ out) {
    int warp = (blockIdx.x * blockDim.x + threadIdx.x) >> 5;
    int lane = threadIdx.x & 31;
    if (warp >= NTOK) return;
    const float* xp = x + (size_t)warp * DIM;
    float4 v0 = *(const float4*)(xp + lane * 4);
    float4 v1 = *(const float4*)(xp + 128 + lane * 4);
    float s  = v0.x + v0.y + v0.z + v0.w + v1.x + v1.y + v1.z + v1.w;
    float ss = v0.x*v0.x + v0.y*v0.y + v0.z*v0.z + v0.w*v0.w
             + v1.x*v1.x + v1.y*v1.y + v1.z*v1.z + v1.w*v1.w;
    #pragma unroll
    for (int o = 16; o > 0; o >>= 1) {
        s  += __shfl_xor_sync(0xffffffffu, s,  o);
        ss += __shfl_xor_sync(0xffffffffu, ss, o);
    }
    float mu  = s * (1.0f / DIM);
    float var = ss * (1.0f / DIM) - mu * mu;
    float inv = rsqrtf(var + 1e-5f);
    float4 g0 = *(const float4*)(g + lane * 4);
    float4 g1 = *(const float4*)(g + 128 + lane * 4);
    float4 b0 = *(const float4*)(b + lane * 4);
    float4 b1 = *(const float4*)(b + 128 + lane * 4);
    __half2 h0 = __floats2half2_rn((v0.x - mu) * inv * g0.x + b0.x,
                                   (v0.y - mu) * inv * g0.y + b0.y);
    __half2 h1 = __floats2half2_rn((v0.z - mu) * inv * g0.z + b0.z,
                                   (v0.w - mu) * inv * g0.w + b0.w);
    __half2 h2 = __floats2half2_rn((v1.x - mu) * inv * g1.x + b1.x,
                                   (v1.y - mu) * inv * g1.y + b1.y);
    __half2 h3 = __floats2half2_rn((v1.z - mu) * inv * g1.z + b1.z,
                                   (v1.w - mu) * inv * g1.w + b1.w);
    __half* op = out + (size_t)warp * DIM;
    ((uint2*)op)[lane]         = make_uint2(*(uint32_t*)&h0, *(uint32_t*)&h1);
    ((uint2*)(op + 128))[lane] = make_uint2(*(uint32_t*)&h2, *(uint32_t*)&h3);
}

// ---------------- fp16 mma.sync GEMM, block 128x128, K-chunk 32 ---------------
// A[M][K] half, Bt[N][K] half (row-major, i.e. B^T). 8 warps 4(M)x2(N),
// warp tile 32x64 = 2x8 m16n8k16 atoms. fp32 accumulate.
#define HSTR 40                             // halves per SMEM row (pad)
#define HSTAGE (128 * HSTR)                 // halves per matrix per stage
#define GSM_TOTAL (4 * HSTAGE * 2)          // 2 stages * (A+B) * 2B = 40960

template<int EPI, typename OT>
__global__ __launch_bounds__(256, 2)
void tc_gemm(const __half* __restrict__ A, const __half* __restrict__ Bt,
             OT* __restrict__ C, int K, int N,
             const float* __restrict__ bias, const float* __restrict__ res) {
    extern __shared__ __half smh[];
    // layout: [s0 A][s0 B][s1 A][s1 B], each 128*HSTR halves
    int tid = threadIdx.x;
    int lane = tid & 31, wid = tid >> 5;
    int warp_m = wid & 3;
    int warp_n = wid >> 2;
    int block_row = blockIdx.y * 128;
    int block_col = blockIdx.x * 128;

    const __half* gA = A  + (size_t)block_row * K;
    const __half* gB = Bt + (size_t)block_col * K;

    uint32_t smA_u[2], smB_u[2];
    smA_u[0] = smem_u32(smh);
    smB_u[0] = smem_u32(smh + HSTAGE);
    smA_u[1] = smem_u32(smh + 2 * HSTAGE);
    smB_u[1] = smem_u32(smh + 3 * HSTAGE);

    auto stage = [&](int c, int s) {
        int c0 = c * 32;
        #pragma unroll
        for (int it = 0; it < 2; ++it) {
            int seg = tid + it * 256;            // 0..511
            int r = seg >> 2, sg = (seg & 3) * 8;
            cp_async16(smA_u[s] + (uint32_t)(r * HSTR + sg) * 2,
                       gA + (size_t)r * K + c0 + sg);
        }
        #pragma unroll
        for (int it = 0; it < 2; ++it) {
            int seg = tid + it * 256;
            int r = seg >> 2, sg = (seg & 3) * 8;
            cp_async16(smB_u[s] + (uint32_t)(r * HSTR + sg) * 2,
                       gB + (size_t)r * K + c0 + sg);
        }
        asm volatile("cp.async.commit_group;");
    };

    float acc[2][8][4];
    #pragma unroll
    for (int i = 0; i < 2; i++)
        #pragma unroll
        for (int j = 0; j < 8; j++)
            #pragma unroll
            for (int q = 0; q < 4; q++) acc[i][j][q] = 0.0f;

    const int nch = K >> 5;
    stage(0, 0);

    int a_row = warp_m * 32 + (lane >> 2);
    int b_row = warp_n * 64 + (lane >> 2);
    int kcol  = (lane & 3) * 2;

    for (int c = 0; c < nch; ++c) {
        int s = c & 1;
        if (c + 1 < nch) {
            stage(c + 1, s ^ 1);
            asm volatile("cp.async.wait_group 1;");
        } else {
            asm volatile("cp.async.wait_group 0;");
        }
        __syncthreads();
        const __half* As = smh + (size_t)s * 2 * HSTAGE;
        const __half* Bs = As + HSTAGE;
        #pragma unroll
        for (int kk = 0; kk < 32; kk += 16) {
            uint32_t a[2][4];
            #pragma unroll
            for (int am = 0; am < 2; ++am) {
                int base = (a_row + am * 16) * HSTR + kcol + kk;
                a[am][0] = *(const uint32_t*)&As[base];
                a[am][1] = *(const uint32_t*)&As[base + 8 * HSTR];
                a[am][2] = *(const uint32_t*)&As[base + 8];
                a[am][3] = *(const uint32_t*)&As[base + 8 * HSTR + 8];
            }
            uint32_t b[8][2];
            #pragma unroll
            for (int bn = 0; bn < 8; ++bn) {
                int base = (b_row + bn * 8) * HSTR + kcol + kk;
                b[bn][0] = *(const uint32_t*)&Bs[base];
                b[bn][1] = *(const uint32_t*)&Bs[base + 8];
            }
            #pragma unroll
            for (int am = 0; am < 2; ++am)
                #pragma unroll
                for (int bn = 0; bn < 8; ++bn)
                    mma_f16(acc[am][bn], a[am], b[bn]);
        }
        __syncthreads();
    }

    #pragma unroll
    for (int am = 0; am < 2; ++am) {
        int row0 = block_row + warp_m * 32 + am * 16 + (lane >> 2);
        #pragma unroll
        for (int bn = 0; bn < 8; ++bn) {
            int col = block_col + warp_n * 64 + bn * 8 + 2 * (lane & 3);
            float2 v0 = make_float2(acc[am][bn][0], acc[am][bn][1]);
            float2 v1 = make_float2(acc[am][bn][2], acc[am][bn][3]);
            if (EPI >= 1) {
                float bx = bias[col], by = bias[col + 1];
                v0.x += bx; v0.y += by; v1.x += bx; v1.y += by;
            }
            if (EPI == 2) {
                v0.x = gelu_exact(v0.x); v0.y = gelu_exact(v0.y);
                v1.x = gelu_exact(v1.x); v1.y = gelu_exact(v1.y);
            }
            if (EPI == 3) {
                const float2 r0 = *(const float2*)&res[(size_t)row0 * N + col];
                const float2 r1 = *(const float2*)&res[(size_t)(row0 + 8) * N + col];
                v0.x += r0.x; v0.y += r0.y; v1.x += r1.x; v1.y += r1.y;
            }
            if constexpr (sizeof(OT) == 2) {
                __half2 h0 = __floats2half2_rn(v0.x, v0.y);
                __half2 h1 = __floats2half2_rn(v1.x, v1.y);
                *(__half2*)&C[(size_t)row0 * N + col]       = h0;
                *(__half2*)&C[(size_t)(row0 + 8) * N + col] = h1;
            } else {
                *(float2*)&C[(size_t)row0 * N + col]       = v0;
                *(float2*)&C[(size_t)(row0 + 8) * N + col] = v1;
            }
        }
    }
}

// ---------------- windowed attention: fp32 in, fp16 out ------------------------
__global__ __launch_bounds__(64) void attn_kernel(
    const float* __restrict__ qkv,
    const float* __restrict__ relb,
    __half* __restrict__ out) {
    int wi = blockIdx.x;
    int h  = blockIdx.y;
    int n  = threadIdx.x;

    __shared__ float sq[64][36];
    __shared__ float sk[64][36];
    __shared__ float sv[64][36];

    int b = wi >> 6, wrem = wi & 63;
    int wh = wrem >> 3, ww = wrem & 7;
    int tok_row = b * 4096 + wh * 8 * 64 + ww * 8;

    {
        int f4 = (n & 7) * 4;
        int tsub = n >> 3;
        #pragma unroll
        for (int it = 0; it < 8; ++it) {
            int t = it * 8 + tsub;
            int ih = t >> 3, iw = t & 7;
            int gt = tok_row + ih * 64 + iw;
            const float* base = qkv + (size_t)gt * QKVC + h * 32 + f4;
            float4 tq = *(const float4*)(base);
            float4 tk = *(const float4*)(base + 256);
            float4 tv = *(const float4*)(base + 512);
            *(float4*)&sq[t][f4] = tq;
            *(float4*)&sk[t][f4] = tk;
            *(float4*)&sv[t][f4] = tv;
        }
    }
    __syncthreads();

    const float scale = 0.17677669529663688f;
    float q[32];
    #pragma unroll
    for (int i = 0; i < 8; i++) {
        float4 v = *(const float4*)&sq[n][4 * i];
        q[4*i+0] = v.x * scale; q[4*i+1] = v.y * scale;
        q[4*i+2] = v.z * scale; q[4*i+3] = v.w * scale;
    }

    int ih = n >> 3, iw = n & 7;
    float mx = -1e30f, sum = 0.0f;
    float o[32];
    #pragma unroll
    for (int d = 0; d < 32; d++) o[d] = 0.0f;

    #pragma unroll 2
    for (int m = 0; m < 64; m++) {
        int jh = m >> 3, jw = m & 7;
        int ridx = (ih - jh + 7) * 15 + (iw - jw + 7);
        float sc = __ldg(&relb[ridx * 8 + h]);
        #pragma unroll
        for (int i = 0; i < 8; i++) {
            float4 kv = *(const float4*)&sk[m][4 * i];
            sc = fmaf(q[4*i+0], kv.x, sc);
            sc = fmaf(q[4*i+1], kv.y, sc);
            sc = fmaf(q[4*i+2], kv.z, sc);
            sc = fmaf(q[4*i+3], kv.w, sc);
        }
        float nm = fmaxf(mx, sc);
        float corr = __expf(mx - nm);
        float p = __expf(sc - nm);
        sum = sum * corr + p;
        #pragma unroll
        for (int i = 0; i < 8; i++) {
            float4 vv = *(const float4*)&sv[m][4 * i];
            o[4*i+0] = fmaf(o[4*i+0], corr, p * vv.x);
            o[4*i+1] = fmaf(o[4*i+1], corr, p * vv.y);
            o[4*i+2] = fmaf(o[4*i+2], corr, p * vv.z);
            o[4*i+3] = fmaf(o[4*i+3], corr, p * vv.w);
        }
        mx = nm;
    }
    float inv = 1.0f / sum;
    #pragma unroll
    for (int i = 0; i < 8; i++) {
        float4 v = make_float4(o[4*i] * inv, o[4*i+1] * inv, o[4*i+2] * inv, o[4*i+3] * inv);
        *(float4*)&sq[n][4 * i] = v;
    }
    __syncthreads();
    {
        int f4 = (n & 7) * 4;
        int tsub = n >> 3;
        #pragma unroll
        for (int it = 0; it < 8; ++it) {
            int t = it * 8 + tsub;
            int th = t >> 3, tw = t & 7;
            int gt = tok_row + th * 64 + tw;
            float4 v = *(const float4*)&sq[t][f4];
            __half2 p0 = __floats2half2_rn(v.x, v.y);
            __half2 p1 = __floats2half2_rn(v.z, v.w);
            *(uint2*)(out + (size_t)gt * DIM + h * 32 + f4) =
                make_uint2(*(uint32_t*)&p0, *(uint32_t*)&p1);
        }
    }
}

// ---------------- launch ------------------------------------------------------
extern "C" void kernel_launch(void* const* d_in, const int* in_sizes, int n_in,
                              void* d_out, int out_size) {
    const float* x      = (const float*)d_in[0];
    const float* ln1_g  = (const float*)d_in[3];
    const float* ln1_b  = (const float*)d_in[4];
    const float* qkv_w  = (const float*)d_in[5];
    const float* proj_w = (const float*)d_in[6];
    const float* proj_b = (const float*)d_in[7];
    const float* relb   = (const float*)d_in[8];
    const float* ln2_g  = (const float*)d_in[9];
    const float* ln2_b  = (const float*)d_in[10];
    const float* fc1_w  = (const float*)d_in[11];
    const float* fc1_b  = (const float*)d_in[12];
    const float* fc2_w  = (const float*)d_in[13];
    const float* fc2_b  = (const float*)d_in[14];
    float* out = (float*)d_out;

    __half *p_lnh, *p_attnh, *p_mlph, *p_wth;
    float  *p_qkv;
    cudaGetSymbolAddress((void**)&p_lnh,   g_lnh);
    cudaGetSymbolAddress((void**)&p_qkv,   g_qkv);
    cudaGetSymbolAddress((void**)&p_attnh, g_attnh);
    cudaGetSymbolAddress((void**)&p_mlph,  g_mlph);
    cudaGetSymbolAddress((void**)&p_wth,   g_wth);

    cudaFuncSetAttribute((const void*)tc_gemm<0, float >, cudaFuncAttributeMaxDynamicSharedMemorySize, GSM_TOTAL);
    cudaFuncSetAttribute((const void*)tc_gemm<2, __half>, cudaFuncAttributeMaxDynamicSharedMemorySize, GSM_TOTAL);
    cudaFuncSetAttribute((const void*)tc_gemm<3, float >, cudaFuncAttributeMaxDynamicSharedMemorySize, GSM_TOTAL);

    transpose_h_kernel<<<dim3(QKVC / 32, DIM / 32), dim3(32, 8)>>>(qkv_w, p_wth + WT_QKV, DIM, QKVC);
    transpose_h_kernel<<<dim3(DIM / 32, DIM / 32),  dim3(32, 8)>>>(proj_w, p_wth + WT_PROJ, DIM, DIM);
    transpose_h_kernel<<<dim3(HID / 32, DIM / 32),  dim3(32, 8)>>>(fc1_w, p_wth + WT_FC1, DIM, HID);
    transpose_h_kernel<<<dim3(DIM / 32, HID / 32),  dim3(32, 8)>>>(fc2_w, p_wth + WT_FC2, HID, DIM);

    // 1. LN1 -> half
    ln_kernel<<<NTOK / 8, 256>>>(x, ln1_g, ln1_b, p_lnh);
    // 2. QKV: [65536,256]h @ [256,768]h -> fp32
    tc_gemm<0, float><<<dim3(QKVC / 128, NTOK / 128), 256, GSM_TOTAL>>>(
        p_lnh, p_wth + WT_QKV, p_qkv, DIM, QKVC, nullptr, nullptr);
    // 3. window attention -> half
    attn_kernel<<<dim3(1024, 8), 64>>>(p_qkv, relb, p_attnh);
    // 4. proj + bias + residual(x) -> out fp32
    tc_gemm<3, float><<<dim3(DIM / 128, NTOK / 128), 256, GSM_TOTAL>>>(
        p_attnh, p_wth + WT_PROJ, out, DIM, DIM, proj_b, x);
    // 5. LN2 -> half
    ln_kernel<<<NTOK / 8, 256>>>(out, ln2_g, ln2_b, p_lnh);
    // 6. fc1 + bias + gelu -> half
    tc_gemm<2, __half><<<dim3(HID / 128, NTOK / 128), 256, GSM_TOTAL>>>(
        p_lnh, p_wth + WT_FC1, p_mlph, DIM, HID, fc1_b, nullptr);
    // 7. fc2 + bias + residual(out) -> out fp32
    tc_gemm<3, float><<<dim3(DIM / 128, NTOK / 128), 256, GSM_TOTAL>>>(
        p_mlph, p_wth + WT_FC2, out, HID, DIM, fc2_b, out);
}

// round 7
// speedup vs baseline: 1.7773x; 1.2199x over previous
#include <cuda_runtime.h>
#include <cuda_fp16.h>
#include <math.h>
#include <stdint.h>

#define NTOK 65536            // 16 * 4096
#define DIM 256
#define QKVC 768
#define HID 1024

// ---------------- scratch ----------------------------------------------------
__device__ __half g_lnh  [(size_t)NTOK * DIM];   // LN output (half)
__device__ __half g_qkvh [(size_t)NTOK * QKVC];  // qkv projection (half)
__device__ __half g_attnh[(size_t)NTOK * DIM];   // attention output (half)
__device__ __half g_mlph [(size_t)NTOK * HID];   // fc1+gelu output (half)
__device__ float  g_bias [8 * 64 * 64];          // per-head rel-pos bias table
#define WT_QKV 0
#define WT_PROJ (QKVC * DIM)
#define WT_FC1  (WT_PROJ + DIM * DIM)
#define WT_FC2  (WT_FC1 + HID * DIM)
__device__ __half g_wth[WT_FC2 + DIM * HID];     // transposed half weights

// ---------------- helpers -----------------------------------------------------
__device__ __forceinline__ uint32_t smem_u32(const void* p) {
    return (uint32_t)__cvta_generic_to_shared((void*)p);
}
__device__ __forceinline__ void cp_async16(uint32_t dst, const void* src) {
    asm volatile("cp.async.cg.shared.global [%0], [%1], 16;" :: "r"(dst), "l"(src));
}
__device__ __forceinline__ float gelu_exact(float v) {
    return 0.5f * v * (1.0f + erff(v * 0.70710678118654752f));
}
__device__ __forceinline__ void mma_f16(float* c, const uint32_t* a, const uint32_t* b) {
    asm volatile(
        "mma.sync.aligned.m16n8k16.row.col.f32.f16.f16.f32 "
        "{%0,%1,%2,%3}, {%4,%5,%6,%7}, {%8,%9}, {%0,%1,%2,%3};"
        : "+f"(c[0]), "+f"(c[1]), "+f"(c[2]), "+f"(c[3])
        : "r"(a[0]), "r"(a[1]), "r"(a[2]), "r"(a[3]), "r"(b[0]), "r"(b[1]));
}
__device__ __forceinline__ void ldm_x4(uint32_t* r, uint32_t addr) {
    asm volatile("ldmatrix.sync.aligned.m8n8.x4.shared.b16 {%0,%1,%2,%3}, [%4];"
                 : "=r"(r[0]), "=r"(r[1]), "=r"(r[2]), "=r"(r[3]) : "r"(addr));
}
__device__ __forceinline__ void ldm_x4_t(uint32_t* r, uint32_t addr) {
    asm volatile("ldmatrix.sync.aligned.m8n8.x4.trans.shared.b16 {%0,%1,%2,%3}, [%4];"
                 : "=r"(r[0]), "=r"(r[1]), "=r"(r[2]), "=r"(r[3]) : "r"(addr));
}
__device__ __forceinline__ uint32_t pack_h2(float a, float b) {
    __half2 h = __floats2half2_rn(a, b);
    return *(uint32_t*)&h;
}

// ---------------- transpose+convert [R][C] f32 -> [C][R] f16 ------------------
__global__ void transpose_h_kernel(const float* __restrict__ in, __half* __restrict__ out,
                                   int R, int C) {
    __shared__ float t[32][33];
    int bx = blockIdx.x * 32, by = blockIdx.y * 32;
    int x = threadIdx.x, y = threadIdx.y;
    #pragma unroll
    for (int j = 0; j < 32; j += 8)
        t[y + j][x] = in[(size_t)(by + y + j) * C + bx + x];
    __syncthreads();
    #pragma unroll
    for (int j = 0; j < 32; j += 8)
        out[(size_t)(bx + y + j) * R + by + x] = __float2half(t[x][y + j]);
}

// ---------------- rel-pos bias table: g_bias[h][i][j] --------------------------
__global__ void bias_kernel(const float* __restrict__ relb, float* __restrict__ gb) {
    int i = blockIdx.x;     // query token in window (0..63)
    int h = blockIdx.y;     // head
    int j = threadIdx.x;    // key token
    int ih = i >> 3, iw = i & 7, jh = j >> 3, jw = j & 7;
    int ridx = (ih - jh + 7) * 15 + (iw - jw + 7);
    gb[h * 4096 + i * 64 + j] = relb[ridx * 8 + h];
}

// ---------------- LayerNorm: one warp per token, fp32 in -> fp16 out ----------
__global__ void ln_kernel(const float* __restrict__ x,
                          const float* __restrict__ g,
                          const float* __restrict__ b,
                          __half* __restrict__ out) {
    int warp = (blockIdx.x * blockDim.x + threadIdx.x) >> 5;
    int lane = threadIdx.x & 31;
    if (warp >= NTOK) return;
    const float* xp = x + (size_t)warp * DIM;
    float4 v0 = *(const float4*)(xp + lane * 4);
    float4 v1 = *(const float4*)(xp + 128 + lane * 4);
    float s  = v0.x + v0.y + v0.z + v0.w + v1.x + v1.y + v1.z + v1.w;
    float ss = v0.x*v0.x + v0.y*v0.y + v0.z*v0.z + v0.w*v0.w
             + v1.x*v1.x + v1.y*v1.y + v1.z*v1.z + v1.w*v1.w;
    #pragma unroll
    for (int o = 16; o > 0; o >>= 1) {
        s  += __shfl_xor_sync(0xffffffffu, s,  o);
        ss += __shfl_xor_sync(0xffffffffu, ss, o);
    }
    float mu  = s * (1.0f / DIM);
    float var = ss * (1.0f / DIM) - mu * mu;
    float inv = rsqrtf(var + 1e-5f);
    float4 g0 = *(const float4*)(g + lane * 4);
    float4 g1 = *(const float4*)(g + 128 + lane * 4);
    float4 b0 = *(const float4*)(b + lane * 4);
    float4 b1 = *(const float4*)(b + 128 + lane * 4);
    __half2 h0 = __floats2half2_rn((v0.x - mu) * inv * g0.x + b0.x,
                                   (v0.y - mu) * inv * g0.y + b0.y);
    __half2 h1 = __floats2half2_rn((v0.z - mu) * inv * g0.z + b0.z,
                                   (v0.w - mu) * inv * g0.w + b0.w);
    __half2 h2 = __floats2half2_rn((v1.x - mu) * inv * g1.x + b1.x,
                                   (v1.y - mu) * inv * g1.y + b1.y);
    __half2 h3 = __floats2half2_rn((v1.z - mu) * inv * g1.z + b1.z,
                                   (v1.w - mu) * inv * g1.w + b1.w);
    __half* op = out + (size_t)warp * DIM;
    ((uint2*)op)[lane]         = make_uint2(*(uint32_t*)&h0, *(uint32_t*)&h1);
    ((uint2*)(op + 128))[lane] = make_uint2(*(uint32_t*)&h2, *(uint32_t*)&h3);
}

// ---------------- fp16 mma.sync GEMM, block 128x128, K-chunk 32 ---------------
#define HSTR 40
#define HSTAGE (128 * HSTR)
#define GSM_TOTAL (4 * HSTAGE * 2)          // 40960

template<int EPI, typename OT>
__global__ __launch_bounds__(256, 2)
void tc_gemm(const __half* __restrict__ A, const __half* __restrict__ Bt,
             OT* __restrict__ C, int K, int N,
             const float* __restrict__ bias, const float* __restrict__ res) {
    extern __shared__ __half smh[];
    int tid = threadIdx.x;
    int lane = tid & 31, wid = tid >> 5;
    int warp_m = wid & 3;
    int warp_n = wid >> 2;
    int block_row = blockIdx.y * 128;
    int block_col = blockIdx.x * 128;

    const __half* gA = A  + (size_t)block_row * K;
    const __half* gB = Bt + (size_t)block_col * K;

    uint32_t smA_u[2], smB_u[2];
    smA_u[0] = smem_u32(smh);
    smB_u[0] = smem_u32(smh + HSTAGE);
    smA_u[1] = smem_u32(smh + 2 * HSTAGE);
    smB_u[1] = smem_u32(smh + 3 * HSTAGE);

    auto stage = [&](int c, int s) {
        int c0 = c * 32;
        #pragma unroll
        for (int it = 0; it < 2; ++it) {
            int seg = tid + it * 256;
            int r = seg >> 2, sg = (seg & 3) * 8;
            cp_async16(smA_u[s] + (uint32_t)(r * HSTR + sg) * 2,
                       gA + (size_t)r * K + c0 + sg);
        }
        #pragma unroll
        for (int it = 0; it < 2; ++it) {
            int seg = tid + it * 256;
            int r = seg >> 2, sg = (seg & 3) * 8;
            cp_async16(smB_u[s] + (uint32_t)(r * HSTR + sg) * 2,
                       gB + (size_t)r * K + c0 + sg);
        }
        asm volatile("cp.async.commit_group;");
    };

    float acc[2][8][4];
    #pragma unroll
    for (int i = 0; i < 2; i++)
        #pragma unroll
        for (int j = 0; j < 8; j++)
            #pragma unroll
            for (int q = 0; q < 4; q++) acc[i][j][q] = 0.0f;

    const int nch = K >> 5;
    stage(0, 0);

    int a_row = warp_m * 32 + (lane >> 2);
    int b_row = warp_n * 64 + (lane >> 2);
    int kcol  = (lane & 3) * 2;

    for (int c = 0; c < nch; ++c) {
        int s = c & 1;
        if (c + 1 < nch) {
            stage(c + 1, s ^ 1);
            asm volatile("cp.async.wait_group 1;");
        } else {
            asm volatile("cp.async.wait_group 0;");
        }
        __syncthreads();
        const __half* As = smh + (size_t)s * 2 * HSTAGE;
        const __half* Bs = As + HSTAGE;
        #pragma unroll
        for (int kk = 0; kk < 32; kk += 16) {
            uint32_t a[2][4];
            #pragma unroll
            for (int am = 0; am < 2; ++am) {
                int base = (a_row + am * 16) * HSTR + kcol + kk;
                a[am][0] = *(const uint32_t*)&As[base];
                a[am][1] = *(const uint32_t*)&As[base + 8 * HSTR];
                a[am][2] = *(const uint32_t*)&As[base + 8];
                a[am][3] = *(const uint32_t*)&As[base + 8 * HSTR + 8];
            }
            uint32_t b[8][2];
            #pragma unroll
            for (int bn = 0; bn < 8; ++bn) {
                int base = (b_row + bn * 8) * HSTR + kcol + kk;
                b[bn][0] = *(const uint32_t*)&Bs[base];
                b[bn][1] = *(const uint32_t*)&Bs[base + 8];
            }
            #pragma unroll
            for (int am = 0; am < 2; ++am)
                #pragma unroll
                for (int bn = 0; bn < 8; ++bn)
                    mma_f16(acc[am][bn], a[am], b[bn]);
        }
        __syncthreads();
    }

    #pragma unroll
    for (int am = 0; am < 2; ++am) {
        int row0 = block_row + warp_m * 32 + am * 16 + (lane >> 2);
        #pragma unroll
        for (int bn = 0; bn < 8; ++bn) {
            int col = block_col + warp_n * 64 + bn * 8 + 2 * (lane & 3);
            float2 v0 = make_float2(acc[am][bn][0], acc[am][bn][1]);
            float2 v1 = make_float2(acc[am][bn][2], acc[am][bn][3]);
            if (EPI >= 1) {
                float bx = bias[col], by = bias[col + 1];
                v0.x += bx; v0.y += by; v1.x += bx; v1.y += by;
            }
            if (EPI == 2) {
                v0.x = gelu_exact(v0.x); v0.y = gelu_exact(v0.y);
                v1.x = gelu_exact(v1.x); v1.y = gelu_exact(v1.y);
            }
            if (EPI == 3) {
                const float2 r0 = *(const float2*)&res[(size_t)row0 * N + col];
                const float2 r1 = *(const float2*)&res[(size_t)(row0 + 8) * N + col];
                v0.x += r0.x; v0.y += r0.y; v1.x += r1.x; v1.y += r1.y;
            }
            if constexpr (sizeof(OT) == 2) {
                __half2 h0 = __floats2half2_rn(v0.x, v0.y);
                __half2 h1 = __floats2half2_rn(v1.x, v1.y);
                *(__half2*)&C[(size_t)row0 * N + col]       = h0;
                *(__half2*)&C[(size_t)(row0 + 8) * N + col] = h1;
            } else {
                *(float2*)&C[(size_t)row0 * N + col]       = v0;
                *(float2*)&C[(size_t)(row0 + 8) * N + col] = v1;
            }
        }
    }
}

// ---------------- tensor-core windowed attention --------------------------------
// block = (window, head), 128 threads / 4 warps; warp owns 16 query rows.
#define QSTR 40   // halves per SMEM row for Q/K/V tiles
#define BSTR 68   // floats per SMEM row for bias tile

__global__ __launch_bounds__(128)
void attn_kernel(const __half* __restrict__ qkv,
                 const float* __restrict__ gbias,
                 __half* __restrict__ out) {
    __shared__ __half sQ[64][QSTR];
    __shared__ __half sK[64][QSTR];
    __shared__ __half sV[64][QSTR];
    __shared__ float  sB[64][BSTR];

    int wi = blockIdx.x;   // window 0..1023
    int h  = blockIdx.y;   // head 0..7
    int tid = threadIdx.x;
    int lane = tid & 31, w = tid >> 5;

    int b = wi >> 6, wrem = wi & 63;
    int wh = wrem >> 3, ww = wrem & 7;
    int tok_row = b * 4096 + wh * 8 * 64 + ww * 8;

    // load Q/K/V tiles: 2 threads per token, 16 halves each
    {
        int t = tid >> 1;
        int part = (tid & 1) * 16;
        int gt = tok_row + (t >> 3) * 64 + (t & 7);
        const __half* src = qkv + (size_t)gt * QKVC + h * 32 + part;
        *(uint4*)&sQ[t][part]     = *(const uint4*)(src);
        *(uint4*)&sQ[t][part + 8] = *(const uint4*)(src + 8);
        *(uint4*)&sK[t][part]     = *(const uint4*)(src + 256);
        *(uint4*)&sK[t][part + 8] = *(const uint4*)(src + 264);
        *(uint4*)&sV[t][part]     = *(const uint4*)(src + 512);
        *(uint4*)&sV[t][part + 8] = *(const uint4*)(src + 520);
    }
    // load bias tile for this head (64x64 f32)
    {
        const float* gb = gbias + h * 4096;
        #pragma unroll
        for (int it = 0; it < 8; ++it) {
            int i4 = tid + it * 128;          // float4 index 0..1023
            int r = i4 >> 4, c4 = (i4 & 15) * 4;
            *(float4*)&sB[r][c4] = *(const float4*)&gb[r * 64 + c4];
        }
    }
    __syncthreads();

    int r0 = w * 16;
    int quad = lane >> 2, tq = lane & 3;
    int r_lo = r0 + quad;            // query rows owned by this thread
    int ldm_row = lane & 7;          // ldmatrix addressing
    int ldm_tile = lane >> 3;        // 0..3

    // ---- S = Q K^T : fragments sacc[atom 0..7][4] ----
    float sacc[8][4];
    #pragma unroll
    for (int a = 0; a < 8; a++)
        #pragma unroll
        for (int q = 0; q < 4; q++) sacc[a][q] = 0.0f;

    #pragma unroll
    for (int kt = 0; kt < 2; ++kt) {
        int k0 = kt * 16;
        uint32_t af[4];
        // A tiles: T0 rows r0..r0+7 cols k0..7, T1 rows+8, T2 cols+8, T3 rows+8 cols+8
        ldm_x4(af, smem_u32(&sQ[r0 + (ldm_tile & 1) * 8 + ldm_row]
                              [k0 + (ldm_tile >> 1) * 8]));
        #pragma unroll
        for (int ap = 0; ap < 4; ++ap) {
            int n0 = ap * 16;
            uint32_t bf[4];
            // B tiles (K rows give B directly): T0 = K[n0..][k0..], T1 = K[n0..][k0+8..],
            // T2 = K[n0+8..][k0..], T3 = K[n0+8..][k0+8..]
            ldm_x4(bf, smem_u32(&sK[n0 + (ldm_tile >> 1) * 8 + ldm_row]
                                  [k0 + (ldm_tile & 1) * 8]));
            mma_f16(sacc[2 * ap],     af, bf);
            mma_f16(sacc[2 * ap + 1], af, bf + 2);
        }
    }

    // ---- scale + bias + softmax (fp32, full row in fragments) ----
    const float scale = 0.17677669529663688f;
    float mx_lo = -1e30f, mx_hi = -1e30f;
    #pragma unroll
    for (int a = 0; a < 8; ++a) {
        int c0 = a * 8 + 2 * tq;
        sacc[a][0] = sacc[a][0] * scale + sB[r_lo][c0];
        sacc[a][1] = sacc[a][1] * scale + sB[r_lo][c0 + 1];
        sacc[a][2] = sacc[a][2] * scale + sB[r_lo + 8][c0];
        sacc[a][3] = sacc[a][3] * scale + sB[r_lo + 8][c0 + 1];
        mx_lo = fmaxf(mx_lo, fmaxf(sacc[a][0], sacc[a][1]));
        mx_hi = fmaxf(mx_hi, fmaxf(sacc[a][2], sacc[a][3]));
    }
    #pragma unroll
    for (int o = 1; o <= 2; o <<= 1) {
        mx_lo = fmaxf(mx_lo, __shfl_xor_sync(0xffffffffu, mx_lo, o));
        mx_hi = fmaxf(mx_hi, __shfl_xor_sync(0xffffffffu, mx_hi, o));
    }
    float sum_lo = 0.0f, sum_hi = 0.0f;
    #pragma unroll
    for (int a = 0; a < 8; ++a) {
        sacc[a][0] = __expf(sacc[a][0] - mx_lo);
        sacc[a][1] = __expf(sacc[a][1] - mx_lo);
        sacc[a][2] = __expf(sacc[a][2] - mx_hi);
        sacc[a][3] = __expf(sacc[a][3] - mx_hi);
        sum_lo += sacc[a][0] + sacc[a][1];
        sum_hi += sacc[a][2] + sacc[a][3];
    }
    #pragma unroll
    for (int o = 1; o <= 2; o <<= 1) {
        sum_lo += __shfl_xor_sync(0xffffffffu, sum_lo, o);
        sum_hi += __shfl_xor_sync(0xffffffffu, sum_hi, o);
    }

    // ---- O = P V : accumulate oacc[dim-atom 0..3][4] ----
    float oacc[4][4];
    #pragma unroll
    for (int a = 0; a < 4; a++)
        #pragma unroll
        for (int q = 0; q < 4; q++) oacc[a][q] = 0.0f;

    #pragma unroll
    for (int kt = 0; kt < 4; ++kt) {
        uint32_t ap_[4];
        ap_[0] = pack_h2(sacc[2*kt][0],     sacc[2*kt][1]);
        ap_[1] = pack_h2(sacc[2*kt][2],     sacc[2*kt][3]);
        ap_[2] = pack_h2(sacc[2*kt+1][0],   sacc[2*kt+1][1]);
        ap_[3] = pack_h2(sacc[2*kt+1][2],   sacc[2*kt+1][3]);
        int k0 = kt * 16;   // key-token offset
        #pragma unroll
        for (int np = 0; np < 2; ++np) {
            int n0 = np * 16;
            uint32_t bf[4];
            // trans tiles: T0 = V[k0..7][n0..7], T1 = V[k0+8..][n0..7],
            // T2 = V[k0..7][n0+8..], T3 = V[k0+8..][n0+8..]
            ldm_x4_t(bf, smem_u32(&sV[k0 + (ldm_tile & 1) * 8 + ldm_row]
                                    [n0 + (ldm_tile >> 1) * 8]));
            mma_f16(oacc[2 * np],     ap_, bf);
            mma_f16(oacc[2 * np + 1], ap_, bf + 2);
        }
    }

    // ---- normalize + store ----
    float inv_lo = 1.0f / sum_lo, inv_hi = 1.0f / sum_hi;
    int gt_lo = tok_row + (r_lo >> 3) * 64 + (r_lo & 7);
    int r_hi = r_lo + 8;
    int gt_hi = tok_row + (r_hi >> 3) * 64 + (r_hi & 7);
    #pragma unroll
    for (int a = 0; a < 4; ++a) {
        int col = h * 32 + a * 8 + 2 * tq;
        __half2 lo = __floats2half2_rn(oacc[a][0] * inv_lo, oacc[a][1] * inv_lo);
        __half2 hi = __floats2half2_rn(oacc[a][2] * inv_hi, oacc[a][3] * inv_hi);
        *(__half2*)&out[(size_t)gt_lo * DIM + col] = lo;
        *(__half2*)&out[(size_t)gt_hi * DIM + col] = hi;
    }
}

// ---------------- launch ------------------------------------------------------
extern "C" void kernel_launch(void* const* d_in, const int* in_sizes, int n_in,
                              void* d_out, int out_size) {
    const float* x      = (const float*)d_in[0];
    const float* ln1_g  = (const float*)d_in[3];
    const float* ln1_b  = (const float*)d_in[4];
    const float* qkv_w  = (const float*)d_in[5];
    const float* proj_w = (const float*)d_in[6];
    const float* proj_b = (const float*)d_in[7];
    const float* relb   = (const float*)d_in[8];
    const float* ln2_g  = (const float*)d_in[9];
    const float* ln2_b  = (const float*)d_in[10];
    const float* fc1_w  = (const float*)d_in[11];
    const float* fc1_b  = (const float*)d_in[12];
    const float* fc2_w  = (const float*)d_in[13];
    const float* fc2_b  = (const float*)d_in[14];
    float* out = (float*)d_out;

    __half *p_lnh, *p_qkvh, *p_attnh, *p_mlph, *p_wth;
    float  *p_bias;
    cudaGetSymbolAddress((void**)&p_lnh,   g_lnh);
    cudaGetSymbolAddress((void**)&p_qkvh,  g_qkvh);
    cudaGetSymbolAddress((void**)&p_attnh, g_attnh);
    cudaGetSymbolAddress((void**)&p_mlph,  g_mlph);
    cudaGetSymbolAddress((void**)&p_wth,   g_wth);
    cudaGetSymbolAddress((void**)&p_bias,  g_bias);

    cudaFuncSetAttribute((const void*)tc_gemm<0, __half>, cudaFuncAttributeMaxDynamicSharedMemorySize, GSM_TOTAL);
    cudaFuncSetAttribute((const void*)tc_gemm<2, __half>, cudaFuncAttributeMaxDynamicSharedMemorySize, GSM_TOTAL);
    cudaFuncSetAttribute((const void*)tc_gemm<3, float >, cudaFuncAttributeMaxDynamicSharedMemorySize, GSM_TOTAL);

    transpose_h_kernel<<<dim3(QKVC / 32, DIM / 32), dim3(32, 8)>>>(qkv_w, p_wth + WT_QKV, DIM, QKVC);
    transpose_h_kernel<<<dim3(DIM / 32, DIM / 32),  dim3(32, 8)>>>(proj_w, p_wth + WT_PROJ, DIM, DIM);
    transpose_h_kernel<<<dim3(HID / 32, DIM / 32),  dim3(32, 8)>>>(fc1_w, p_wth + WT_FC1, DIM, HID);
    transpose_h_kernel<<<dim3(DIM / 32, HID / 32),  dim3(32, 8)>>>(fc2_w, p_wth + WT_FC2, HID, DIM);
    bias_kernel<<<dim3(64, 8), 64>>>(relb, p_bias);

    // 1. LN1 -> half
    ln_kernel<<<NTOK / 8, 256>>>(x, ln1_g, ln1_b, p_lnh);
    // 2. QKV: -> half
    tc_gemm<0, __half><<<dim3(QKVC / 128, NTOK / 128), 256, GSM_TOTAL>>>(
        p_lnh, p_wth + WT_QKV, p_qkvh, DIM, QKVC, nullptr, nullptr);
    // 3. tensor-core window attention -> half
    attn_kernel<<<dim3(1024, 8), 128>>>(p_qkvh, p_bias, p_attnh);
    // 4. proj + bias + residual(x) -> out fp32
    tc_gemm<3, float><<<dim3(DIM / 128, NTOK / 128), 256, GSM_TOTAL>>>(
        p_attnh, p_wth + WT_PROJ, out, DIM, DIM, proj_b, x);
    // 5. LN2 -> half
    ln_kernel<<<NTOK / 8, 256>>>(out, ln2_g, ln2_b, p_lnh);
    // 6. fc1 + bias + gelu -> half
    tc_gemm<2, __half><<<dim3(HID / 128, NTOK / 128), 256, GSM_TOTAL>>>(
        p_lnh, p_wth + WT_FC1, p_mlph, DIM, HID, fc1_b, nullptr);
    // 7. fc2 + bias + residual(out) -> out fp32
    tc_gemm<3, float><<<dim3(DIM / 128, NTOK / 128), 256, GSM_TOTAL>>>(
        p_mlph, p_wth + WT_FC2, out, HID, DIM, fc2_b, out);
}

// round 8
// speedup vs baseline: 1.8795x; 1.0575x over previous
#include <cuda_runtime.h>
#include <cuda_fp16.h>
#include <math.h>
#include <stdint.h>

#define NTOK 65536            // 16 * 4096
#define DIM 256
#define QKVC 768
#define HID 1024

// ---------------- scratch ----------------------------------------------------
__device__ __half g_lnh  [(size_t)NTOK * DIM];   // LN output (half)
__device__ __half g_qkvh [(size_t)NTOK * QKVC];  // qkv projection (half)
__device__ __half g_attnh[(size_t)NTOK * DIM];   // attention output (half)
__device__ __half g_mlph [(size_t)NTOK * HID];   // fc1+gelu output (half)
__device__ float  g_bias [8 * 64 * 64];          // per-head rel-pos bias table
#define WT_QKV 0
#define WT_PROJ (QKVC * DIM)
#define WT_FC1  (WT_PROJ + DIM * DIM)
#define WT_FC2  (WT_FC1 + HID * DIM)
__device__ __half g_wth[WT_FC2 + DIM * HID];     // transposed half weights

// ---------------- helpers -----------------------------------------------------
__device__ __forceinline__ uint32_t smem_u32(const void* p) {
    return (uint32_t)__cvta_generic_to_shared((void*)p);
}
__device__ __forceinline__ void cp_async16(uint32_t dst, const void* src) {
    asm volatile("cp.async.cg.shared.global [%0], [%1], 16;" :: "r"(dst), "l"(src));
}
__device__ __forceinline__ float gelu_exact(float v) {
    return 0.5f * v * (1.0f + erff(v * 0.70710678118654752f));
}
__device__ __forceinline__ void mma_f16(float* c, const uint32_t* a, const uint32_t* b) {
    asm volatile(
        "mma.sync.aligned.m16n8k16.row.col.f32.f16.f16.f32 "
        "{%0,%1,%2,%3}, {%4,%5,%6,%7}, {%8,%9}, {%0,%1,%2,%3};"
        : "+f"(c[0]), "+f"(c[1]), "+f"(c[2]), "+f"(c[3])
        : "r"(a[0]), "r"(a[1]), "r"(a[2]), "r"(a[3]), "r"(b[0]), "r"(b[1]));
}
__device__ __forceinline__ void ldm_x4(uint32_t* r, uint32_t addr) {
    asm volatile("ldmatrix.sync.aligned.m8n8.x4.shared.b16 {%0,%1,%2,%3}, [%4];"
                 : "=r"(r[0]), "=r"(r[1]), "=r"(r[2]), "=r"(r[3]) : "r"(addr));
}
__device__ __forceinline__ void ldm_x4_t(uint32_t* r, uint32_t addr) {
    asm volatile("ldmatrix.sync.aligned.m8n8.x4.trans.shared.b16 {%0,%1,%2,%3}, [%4];"
                 : "=r"(r[0]), "=r"(r[1]), "=r"(r[2]), "=r"(r[3]) : "r"(addr));
}
__device__ __forceinline__ uint32_t pack_h2(float a, float b) {
    __half2 h = __floats2half2_rn(a, b);
    return *(uint32_t*)&h;
}

// ---------------- transpose+convert [R][C] f32 -> [C][R] f16 ------------------
__global__ void transpose_h_kernel(const float* __restrict__ in, __half* __restrict__ out,
                                   int R, int C) {
    __shared__ float t[32][33];
    int bx = blockIdx.x * 32, by = blockIdx.y * 32;
    int x = threadIdx.x, y = threadIdx.y;
    #pragma unroll
    for (int j = 0; j < 32; j += 8)
        t[y + j][x] = in[(size_t)(by + y + j) * C + bx + x];
    __syncthreads();
    #pragma unroll
    for (int j = 0; j < 32; j += 8)
        out[(size_t)(bx + y + j) * R + by + x] = __float2half(t[x][y + j]);
}

// ---------------- rel-pos bias table: g_bias[h][i][j] --------------------------
__global__ void bias_kernel(const float* __restrict__ relb, float* __restrict__ gb) {
    int i = blockIdx.x;
    int h = blockIdx.y;
    int j = threadIdx.x;
    int ih = i >> 3, iw = i & 7, jh = j >> 3, jw = j & 7;
    int ridx = (ih - jh + 7) * 15 + (iw - jw + 7);
    gb[h * 4096 + i * 64 + j] = relb[ridx * 8 + h];
}

// ---------------- LayerNorm: one warp per token, fp32 in -> fp16 out ----------
__global__ void ln_kernel(const float* __restrict__ x,
                          const float* __restrict__ g,
                          const float* __restrict__ b,
                          __half* __restrict__ out) {
    int warp = (blockIdx.x * blockDim.x + threadIdx.x) >> 5;
    int lane = threadIdx.x & 31;
    if (warp >= NTOK) return;
    const float* xp = x + (size_t)warp * DIM;
    float4 v0 = *(const float4*)(xp + lane * 4);
    float4 v1 = *(const float4*)(xp + 128 + lane * 4);
    float s  = v0.x + v0.y + v0.z + v0.w + v1.x + v1.y + v1.z + v1.w;
    float ss = v0.x*v0.x + v0.y*v0.y + v0.z*v0.z + v0.w*v0.w
             + v1.x*v1.x + v1.y*v1.y + v1.z*v1.z + v1.w*v1.w;
    #pragma unroll
    for (int o = 16; o > 0; o >>= 1) {
        s  += __shfl_xor_sync(0xffffffffu, s,  o);
        ss += __shfl_xor_sync(0xffffffffu, ss, o);
    }
    float mu  = s * (1.0f / DIM);
    float var = ss * (1.0f / DIM) - mu * mu;
    float inv = rsqrtf(var + 1e-5f);
    float4 g0 = *(const float4*)(g + lane * 4);
    float4 g1 = *(const float4*)(g + 128 + lane * 4);
    float4 b0 = *(const float4*)(b + lane * 4);
    float4 b1 = *(const float4*)(b + 128 + lane * 4);
    __half2 h0 = __floats2half2_rn((v0.x - mu) * inv * g0.x + b0.x,
                                   (v0.y - mu) * inv * g0.y + b0.y);
    __half2 h1 = __floats2half2_rn((v0.z - mu) * inv * g0.z + b0.z,
                                   (v0.w - mu) * inv * g0.w + b0.w);
    __half2 h2 = __floats2half2_rn((v1.x - mu) * inv * g1.x + b1.x,
                                   (v1.y - mu) * inv * g1.y + b1.y);
    __half2 h3 = __floats2half2_rn((v1.z - mu) * inv * g1.z + b1.z,
                                   (v1.w - mu) * inv * g1.w + b1.w);
    __half* op = out + (size_t)warp * DIM;
    ((uint2*)op)[lane]         = make_uint2(*(uint32_t*)&h0, *(uint32_t*)&h1);
    ((uint2*)(op + 128))[lane] = make_uint2(*(uint32_t*)&h2, *(uint32_t*)&h3);
}

// ---------------- fp16 mma.sync GEMM, block 128x128, K-chunk 32, 3 stages -----
#define HSTR 40
#define HSTAGE (128 * HSTR)                 // halves per matrix per stage
#define STG    (2 * HSTAGE)                 // halves per stage (A+B)
#define GSM_TOTAL (3 * STG * 2)             // 61440 bytes

template<int EPI, typename OT>
__global__ __launch_bounds__(256, 2)
void tc_gemm(const __half* __restrict__ A, const __half* __restrict__ Bt,
             OT* __restrict__ C, int K, int N,
             const float* __restrict__ bias, const float* __restrict__ res) {
    extern __shared__ __half smh[];
    int tid = threadIdx.x;
    int lane = tid & 31, wid = tid >> 5;
    int warp_m = wid & 3;
    int warp_n = wid >> 2;
    int block_row = blockIdx.y * 128;
    int block_col = blockIdx.x * 128;

    const __half* gA = A  + (size_t)block_row * K;
    const __half* gB = Bt + (size_t)block_col * K;

    // stage chunk (absolute index c) into buffer c%3
    auto stage = [&](int c) {
        int s = c % 3;
        int c0 = c * 32;
        uint32_t smA = smem_u32(smh + (size_t)s * STG);
        uint32_t smB = smA + HSTAGE * 2;
        #pragma unroll
        for (int it = 0; it < 2; ++it) {
            int seg = tid + it * 256;
            int r = seg >> 2, sg = (seg & 3) * 8;
            cp_async16(smA + (uint32_t)(r * HSTR + sg) * 2,
                       gA + (size_t)r * K + c0 + sg);
        }
        #pragma unroll
        for (int it = 0; it < 2; ++it) {
            int seg = tid + it * 256;
            int r = seg >> 2, sg = (seg & 3) * 8;
            cp_async16(smB + (uint32_t)(r * HSTR + sg) * 2,
                       gB + (size_t)r * K + c0 + sg);
        }
        asm volatile("cp.async.commit_group;");
    };

    float acc[2][8][4];
    #pragma unroll
    for (int i = 0; i < 2; i++)
        #pragma unroll
        for (int j = 0; j < 8; j++)
            #pragma unroll
            for (int q = 0; q < 4; q++) acc[i][j][q] = 0.0f;

    const int nch = K >> 5;
    stage(0);
    if (nch > 1) stage(1);

    int ldm_row  = lane & 7;     // row within 8x8 tile
    int ldm_tile = lane >> 3;    // which tile (0..3)

    // A ldmatrix: row = warp_m*32 + am*16 + (tile&1)*8 + ldm_row, col = kk + (tile>>1)*8
    int a_roff = warp_m * 32 + (ldm_tile & 1) * 8 + ldm_row;
    int a_coff = (ldm_tile >> 1) * 8;
    // B ldmatrix: row = warp_n*64 + bp*16 + (tile>>1)*8 + ldm_row, col = kk + (tile&1)*8
    int b_roff = warp_n * 64 + (ldm_tile >> 1) * 8 + ldm_row;
    int b_coff = (ldm_tile & 1) * 8;

    for (int c = 0; c < nch; ++c) {
        if (c + 2 < nch) {
            stage(c + 2);
            asm volatile("cp.async.wait_group 2;");
        } else if (c + 1 < nch) {
            asm volatile("cp.async.wait_group 1;");
        } else {
            asm volatile("cp.async.wait_group 0;");
        }
        __syncthreads();
        int s = c % 3;
        uint32_t As = smem_u32(smh + (size_t)s * STG);
        uint32_t Bs = As + HSTAGE * 2;
        #pragma unroll
        for (int kk = 0; kk < 32; kk += 16) {
            uint32_t a[2][4];
            #pragma unroll
            for (int am = 0; am < 2; ++am)
                ldm_x4(a[am], As + (uint32_t)((a_roff + am * 16) * HSTR + kk + a_coff) * 2);
            uint32_t b[4][4];
            #pragma unroll
            for (int bp = 0; bp < 4; ++bp)
                ldm_x4(b[bp], Bs + (uint32_t)((b_roff + bp * 16) * HSTR + kk + b_coff) * 2);
            #pragma unroll
            for (int am = 0; am < 2; ++am)
                #pragma unroll
                for (int bp = 0; bp < 4; ++bp) {
                    mma_f16(acc[am][2 * bp],     a[am], b[bp]);
                    mma_f16(acc[am][2 * bp + 1], a[am], b[bp] + 2);
                }
        }
        __syncthreads();
    }

    #pragma unroll
    for (int am = 0; am < 2; ++am) {
        int row0 = block_row + warp_m * 32 + am * 16 + (lane >> 2);
        #pragma unroll
        for (int bn = 0; bn < 8; ++bn) {
            int col = block_col + warp_n * 64 + bn * 8 + 2 * (lane & 3);
            float2 v0 = make_float2(acc[am][bn][0], acc[am][bn][1]);
            float2 v1 = make_float2(acc[am][bn][2], acc[am][bn][3]);
            if (EPI >= 1) {
                float bx = bias[col], by = bias[col + 1];
                v0.x += bx; v0.y += by; v1.x += bx; v1.y += by;
            }
            if (EPI == 2) {
                v0.x = gelu_exact(v0.x); v0.y = gelu_exact(v0.y);
                v1.x = gelu_exact(v1.x); v1.y = gelu_exact(v1.y);
            }
            if (EPI == 3) {
                const float2 r0 = *(const float2*)&res[(size_t)row0 * N + col];
                const float2 r1 = *(const float2*)&res[(size_t)(row0 + 8) * N + col];
                v0.x += r0.x; v0.y += r0.y; v1.x += r1.x; v1.y += r1.y;
            }
            if constexpr (sizeof(OT) == 2) {
                __half2 h0 = __floats2half2_rn(v0.x, v0.y);
                __half2 h1 = __floats2half2_rn(v1.x, v1.y);
                *(__half2*)&C[(size_t)row0 * N + col]       = h0;
                *(__half2*)&C[(size_t)(row0 + 8) * N + col] = h1;
            } else {
                *(float2*)&C[(size_t)row0 * N + col]       = v0;
                *(float2*)&C[(size_t)(row0 + 8) * N + col] = v1;
            }
        }
    }
}

// ---------------- tensor-core windowed attention --------------------------------
#define QSTR 40
#define BSTR 68

__global__ __launch_bounds__(128)
void attn_kernel(const __half* __restrict__ qkv,
                 const float* __restrict__ gbias,
                 __half* __restrict__ out) {
    __shared__ __half sQ[64][QSTR];
    __shared__ __half sK[64][QSTR];
    __shared__ __half sV[64][QSTR];
    __shared__ float  sB[64][BSTR];

    int wi = blockIdx.x;
    int h  = blockIdx.y;
    int tid = threadIdx.x;
    int lane = tid & 31, w = tid >> 5;

    int b = wi >> 6, wrem = wi & 63;
    int wh = wrem >> 3, ww = wrem & 7;
    int tok_row = b * 4096 + wh * 8 * 64 + ww * 8;

    {
        int t = tid >> 1;
        int part = (tid & 1) * 16;
        int gt = tok_row + (t >> 3) * 64 + (t & 7);
        const __half* src = qkv + (size_t)gt * QKVC + h * 32 + part;
        *(uint4*)&sQ[t][part]     = *(const uint4*)(src);
        *(uint4*)&sQ[t][part + 8] = *(const uint4*)(src + 8);
        *(uint4*)&sK[t][part]     = *(const uint4*)(src + 256);
        *(uint4*)&sK[t][part + 8] = *(const uint4*)(src + 264);
        *(uint4*)&sV[t][part]     = *(const uint4*)(src + 512);
        *(uint4*)&sV[t][part + 8] = *(const uint4*)(src + 520);
    }
    {
        const float* gb = gbias + h * 4096;
        #pragma unroll
        for (int it = 0; it < 8; ++it) {
            int i4 = tid + it * 128;
            int r = i4 >> 4, c4 = (i4 & 15) * 4;
            *(float4*)&sB[r][c4] = *(const float4*)&gb[r * 64 + c4];
        }
    }
    __syncthreads();

    int r0 = w * 16;
    int quad = lane >> 2, tq = lane & 3;
    int r_lo = r0 + quad;
    int ldm_row = lane & 7;
    int ldm_tile = lane >> 3;

    float sacc[8][4];
    #pragma unroll
    for (int a = 0; a < 8; a++)
        #pragma unroll
        for (int q = 0; q < 4; q++) sacc[a][q] = 0.0f;

    #pragma unroll
    for (int kt = 0; kt < 2; ++kt) {
        int k0 = kt * 16;
        uint32_t af[4];
        ldm_x4(af, smem_u32(&sQ[r0 + (ldm_tile & 1) * 8 + ldm_row]
                              [k0 + (ldm_tile >> 1) * 8]));
        #pragma unroll
        for (int ap = 0; ap < 4; ++ap) {
            int n0 = ap * 16;
            uint32_t bf[4];
            ldm_x4(bf, smem_u32(&sK[n0 + (ldm_tile >> 1) * 8 + ldm_row]
                                  [k0 + (ldm_tile & 1) * 8]));
            mma_f16(sacc[2 * ap],     af, bf);
            mma_f16(sacc[2 * ap + 1], af, bf + 2);
        }
    }

    const float scale = 0.17677669529663688f;
    float mx_lo = -1e30f, mx_hi = -1e30f;
    #pragma unroll
    for (int a = 0; a < 8; ++a) {
        int c0 = a * 8 + 2 * tq;
        sacc[a][0] = sacc[a][0] * scale + sB[r_lo][c0];
        sacc[a][1] = sacc[a][1] * scale + sB[r_lo][c0 + 1];
        sacc[a][2] = sacc[a][2] * scale + sB[r_lo + 8][c0];
        sacc[a][3] = sacc[a][3] * scale + sB[r_lo + 8][c0 + 1];
        mx_lo = fmaxf(mx_lo, fmaxf(sacc[a][0], sacc[a][1]));
        mx_hi = fmaxf(mx_hi, fmaxf(sacc[a][2], sacc[a][3]));
    }
    #pragma unroll
    for (int o = 1; o <= 2; o <<= 1) {
        mx_lo = fmaxf(mx_lo, __shfl_xor_sync(0xffffffffu, mx_lo, o));
        mx_hi = fmaxf(mx_hi, __shfl_xor_sync(0xffffffffu, mx_hi, o));
    }
    float sum_lo = 0.0f, sum_hi = 0.0f;
    #pragma unroll
    for (int a = 0; a < 8; ++a) {
        sacc[a][0] = __expf(sacc[a][0] - mx_lo);
        sacc[a][1] = __expf(sacc[a][1] - mx_lo);
        sacc[a][2] = __expf(sacc[a][2] - mx_hi);
        sacc[a][3] = __expf(sacc[a][3] - mx_hi);
        sum_lo += sacc[a][0] + sacc[a][1];
        sum_hi += sacc[a][2] + sacc[a][3];
    }
    #pragma unroll
    for (int o = 1; o <= 2; o <<= 1) {
        sum_lo += __shfl_xor_sync(0xffffffffu, sum_lo, o);
        sum_hi += __shfl_xor_sync(0xffffffffu, sum_hi, o);
    }

    float oacc[4][4];
    #pragma unroll
    for (int a = 0; a < 4; a++)
        #pragma unroll
        for (int q = 0; q < 4; q++) oacc[a][q] = 0.0f;

    #pragma unroll
    for (int kt = 0; kt < 4; ++kt) {
        uint32_t ap_[4];
        ap_[0] = pack_h2(sacc[2*kt][0],     sacc[2*kt][1]);
        ap_[1] = pack_h2(sacc[2*kt][2],     sacc[2*kt][3]);
        ap_[2] = pack_h2(sacc[2*kt+1][0],   sacc[2*kt+1][1]);
        ap_[3] = pack_h2(sacc[2*kt+1][2],   sacc[2*kt+1][3]);
        int k0 = kt * 16;
        #pragma unroll
        for (int np = 0; np < 2; ++np) {
            int n0 = np * 16;
            uint32_t bf[4];
            ldm_x4_t(bf, smem_u32(&sV[k0 + (ldm_tile & 1) * 8 + ldm_row]
                                    [n0 + (ldm_tile >> 1) * 8]));
            mma_f16(oacc[2 * np],     ap_, bf);
            mma_f16(oacc[2 * np + 1], ap_, bf + 2);
        }
    }

    float inv_lo = 1.0f / sum_lo, inv_hi = 1.0f / sum_hi;
    int gt_lo = tok_row + (r_lo >> 3) * 64 + (r_lo & 7);
    int r_hi = r_lo + 8;
    int gt_hi = tok_row + (r_hi >> 3) * 64 + (r_hi & 7);
    #pragma unroll
    for (int a = 0; a < 4; ++a) {
        int col = h * 32 + a * 8 + 2 * tq;
        __half2 lo = __floats2half2_rn(oacc[a][0] * inv_lo, oacc[a][1] * inv_lo);
        __half2 hi = __floats2half2_rn(oacc[a][2] * inv_hi, oacc[a][3] * inv_hi);
        *(__half2*)&out[(size_t)gt_lo * DIM + col] = lo;
        *(__half2*)&out[(size_t)gt_hi * DIM + col] = hi;
    }
}

// ---------------- launch ------------------------------------------------------
extern "C" void kernel_launch(void* const* d_in, const int* in_sizes, int n_in,
                              void* d_out, int out_size) {
    const float* x      = (const float*)d_in[0];
    const float* ln1_g  = (const float*)d_in[3];
    const float* ln1_b  = (const float*)d_in[4];
    const float* qkv_w  = (const float*)d_in[5];
    const float* proj_w = (const float*)d_in[6];
    const float* proj_b = (const float*)d_in[7];
    const float* relb   = (const float*)d_in[8];
    const float* ln2_g  = (const float*)d_in[9];
    const float* ln2_b  = (const float*)d_in[10];
    const float* fc1_w  = (const float*)d_in[11];
    const float* fc1_b  = (const float*)d_in[12];
    const float* fc2_w  = (const float*)d_in[13];
    const float* fc2_b  = (const float*)d_in[14];
    float* out = (float*)d_out;

    __half *p_lnh, *p_qkvh, *p_attnh, *p_mlph, *p_wth;
    float  *p_bias;
    cudaGetSymbolAddress((void**)&p_lnh,   g_lnh);
    cudaGetSymbolAddress((void**)&p_qkvh,  g_qkvh);
    cudaGetSymbolAddress((void**)&p_attnh, g_attnh);
    cudaGetSymbolAddress((void**)&p_mlph,  g_mlph);
    cudaGetSymbolAddress((void**)&p_wth,   g_wth);
    cudaGetSymbolAddress((void**)&p_bias,  g_bias);

    cudaFuncSetAttribute((const void*)tc_gemm<0, __half>, cudaFuncAttributeMaxDynamicSharedMemorySize, GSM_TOTAL);
    cudaFuncSetAttribute((const void*)tc_gemm<2, __half>, cudaFuncAttributeMaxDynamicSharedMemorySize, GSM_TOTAL);
    cudaFuncSetAttribute((const void*)tc_gemm<3, float >, cudaFuncAttributeMaxDynamicSharedMemorySize, GSM_TOTAL);

    transpose_h_kernel<<<dim3(QKVC / 32, DIM / 32), dim3(32, 8)>>>(qkv_w, p_wth + WT_QKV, DIM, QKVC);
    transpose_h_kernel<<<dim3(DIM / 32, DIM / 32),  dim3(32, 8)>>>(proj_w, p_wth + WT_PROJ, DIM, DIM);
    transpose_h_kernel<<<dim3(HID / 32, DIM / 32),  dim3(32, 8)>>>(fc1_w, p_wth + WT_FC1, DIM, HID);
    transpose_h_kernel<<<dim3(DIM / 32, HID / 32),  dim3(32, 8)>>>(fc2_w, p_wth + WT_FC2, HID, DIM);
    bias_kernel<<<dim3(64, 8), 64>>>(relb, p_bias);

    // 1. LN1 -> half
    ln_kernel<<<NTOK / 8, 256>>>(x, ln1_g, ln1_b, p_lnh);
    // 2. QKV -> half
    tc_gemm<0, __half><<<dim3(QKVC / 128, NTOK / 128), 256, GSM_TOTAL>>>(
        p_lnh, p_wth + WT_QKV, p_qkvh, DIM, QKVC, nullptr, nullptr);
    // 3. tensor-core window attention -> half
    attn_kernel<<<dim3(1024, 8), 128>>>(p_qkvh, p_bias, p_attnh);
    // 4. proj + bias + residual(x) -> out fp32
    tc_gemm<3, float><<<dim3(DIM / 128, NTOK / 128), 256, GSM_TOTAL>>>(
        p_attnh, p_wth + WT_PROJ, out, DIM, DIM, proj_b, x);
    // 5. LN2 -> half
    ln_kernel<<<NTOK / 8, 256>>>(out, ln2_g, ln2_b, p_lnh);
    // 6. fc1 + bias + gelu -> half
    tc_gemm<2, __half><<<dim3(HID / 128, NTOK / 128), 256, GSM_TOTAL>>>(
        p_lnh, p_wth + WT_FC1, p_mlph, DIM, HID, fc1_b, nullptr);
    // 7. fc2 + bias + residual(out) -> out fp32
    tc_gemm<3, float><<<dim3(DIM / 128, NTOK / 128), 256, GSM_TOTAL>>>(
        p_mlph, p_wth + WT_FC2, out, HID, DIM, fc2_b, out);
}

// round 9
// speedup vs baseline: 2.0120x; 1.0705x over previous
#include <cuda_runtime.h>
#include <cuda_fp16.h>
#include <math.h>
#include <stdint.h>

#define NTOK 65536            // 16 * 4096
#define DIM 256
#define QKVC 768
#define HID 1024

// ---------------- scratch ----------------------------------------------------
__device__ __half g_lnh  [(size_t)NTOK * DIM];
__device__ __half g_qkvh [(size_t)NTOK * QKVC];
__device__ __half g_attnh[(size_t)NTOK * DIM];
__device__ __half g_mlph [(size_t)NTOK * HID];
__device__ float  g_bias [8 * 64 * 64];
#define WT_QKV 0
#define WT_PROJ (QKVC * DIM)
#define WT_FC1  (WT_PROJ + DIM * DIM)
#define WT_FC2  (WT_FC1 + HID * DIM)
__device__ __half g_wth[WT_FC2 + DIM * HID];

// ---------------- helpers -----------------------------------------------------
__device__ __forceinline__ uint32_t smem_u32(const void* p) {
    return (uint32_t)__cvta_generic_to_shared((void*)p);
}
__device__ __forceinline__ void cp_async16(uint32_t dst, const void* src) {
    asm volatile("cp.async.cg.shared.global [%0], [%1], 16;" :: "r"(dst), "l"(src));
}
__device__ __forceinline__ float gelu_exact(float v) {
    return 0.5f * v * (1.0f + erff(v * 0.70710678118654752f));
}
__device__ __forceinline__ void mma_f16(float* c, const uint32_t* a, const uint32_t* b) {
    asm volatile(
        "mma.sync.aligned.m16n8k16.row.col.f32.f16.f16.f32 "
        "{%0,%1,%2,%3}, {%4,%5,%6,%7}, {%8,%9}, {%0,%1,%2,%3};"
        : "+f"(c[0]), "+f"(c[1]), "+f"(c[2]), "+f"(c[3])
        : "r"(a[0]), "r"(a[1]), "r"(a[2]), "r"(a[3]), "r"(b[0]), "r"(b[1]));
}
__device__ __forceinline__ void ldm_x4(uint32_t* r, uint32_t addr) {
    asm volatile("ldmatrix.sync.aligned.m8n8.x4.shared.b16 {%0,%1,%2,%3}, [%4];"
                 : "=r"(r[0]), "=r"(r[1]), "=r"(r[2]), "=r"(r[3]) : "r"(addr));
}
__device__ __forceinline__ void ldm_x4_t(uint32_t* r, uint32_t addr) {
    asm volatile("ldmatrix.sync.aligned.m8n8.x4.trans.shared.b16 {%0,%1,%2,%3}, [%4];"
                 : "=r"(r[0]), "=r"(r[1]), "=r"(r[2]), "=r"(r[3]) : "r"(addr));
}
__device__ __forceinline__ uint32_t pack_h2(float a, float b) {
    __half2 h = __floats2half2_rn(a, b);
    return *(uint32_t*)&h;
}

// ---------------- fused prep: 4 weight transposes + bias table ----------------
// blocks 0..191 QKV, 192..255 proj, 256..511 fc1, 512..767 fc2, 768..775 bias
__global__ void prep_kernel(const float* __restrict__ qkv_w,
                            const float* __restrict__ proj_w,
                            const float* __restrict__ fc1_w,
                            const float* __restrict__ fc2_w,
                            const float* __restrict__ relb,
                            __half* __restrict__ wt, float* __restrict__ gb) {
    int blk = blockIdx.x;
    int x = threadIdx.x, y = threadIdx.y;
    if (blk >= 768) {            // bias table
        int h = blk - 768;
        int tid = y * 32 + x;
        #pragma unroll
        for (int it = 0; it < 16; ++it) {
            int e = tid + it * 256;       // 0..4095
            int i = e >> 6, j = e & 63;
            int ridx = ((i >> 3) - (j >> 3) + 7) * 15 + ((i & 7) - (j & 7) + 7);
            gb[h * 4096 + e] = relb[ridx * 8 + h];
        }
        return;
    }
    const float* in; __half* out; int R, C, bx, by;
    if (blk < 192)      { in = qkv_w;  out = wt + WT_QKV;  R = DIM; C = QKVC;
                          int i = blk;       bx = (i % 24) * 32; by = (i / 24) * 32; }
    else if (blk < 256) { in = proj_w; out = wt + WT_PROJ; R = DIM; C = DIM;
                          int i = blk - 192; bx = (i % 8) * 32;  by = (i / 8) * 32; }
    else if (blk < 512) { in = fc1_w;  out = wt + WT_FC1;  R = DIM; C = HID;
                          int i = blk - 256; bx = (i % 32) * 32; by = (i / 32) * 32; }
    else                { in = fc2_w;  out = wt + WT_FC2;  R = HID; C = DIM;
                          int i = blk - 512; bx = (i % 8) * 32;  by = (i / 8) * 32; }
    __shared__ float t[32][33];
    #pragma unroll
    for (int j = 0; j < 32; j += 8)
        t[y + j][x] = in[(size_t)(by + y + j) * C + bx + x];
    __syncthreads();
    #pragma unroll
    for (int j = 0; j < 32; j += 8)
        out[(size_t)(bx + y + j) * R + by + x] = __float2half(t[x][y + j]);
}

// ---------------- LayerNorm: one warp per token, fp32 in -> fp16 out ----------
__global__ void ln_kernel(const float* __restrict__ x,
                          const float* __restrict__ g,
                          const float* __restrict__ b,
                          __half* __restrict__ out) {
    int warp = (blockIdx.x * blockDim.x + threadIdx.x) >> 5;
    int lane = threadIdx.x & 31;
    if (warp >= NTOK) return;
    const float* xp = x + (size_t)warp * DIM;
    float4 v0 = *(const float4*)(xp + lane * 4);
    float4 v1 = *(const float4*)(xp + 128 + lane * 4);
    float s  = v0.x + v0.y + v0.z + v0.w + v1.x + v1.y + v1.z + v1.w;
    float ss = v0.x*v0.x + v0.y*v0.y + v0.z*v0.z + v0.w*v0.w
             + v1.x*v1.x + v1.y*v1.y + v1.z*v1.z + v1.w*v1.w;
    #pragma unroll
    for (int o = 16; o > 0; o >>= 1) {
        s  += __shfl_xor_sync(0xffffffffu, s,  o);
        ss += __shfl_xor_sync(0xffffffffu, ss, o);
    }
    float mu  = s * (1.0f / DIM);
    float var = ss * (1.0f / DIM) - mu * mu;
    float inv = rsqrtf(var + 1e-5f);
    float4 g0 = *(const float4*)(g + lane * 4);
    float4 g1 = *(const float4*)(g + 128 + lane * 4);
    float4 b0 = *(const float4*)(b + lane * 4);
    float4 b1 = *(const float4*)(b + 128 + lane * 4);
    __half2 h0 = __floats2half2_rn((v0.x - mu) * inv * g0.x + b0.x,
                                   (v0.y - mu) * inv * g0.y + b0.y);
    __half2 h1 = __floats2half2_rn((v0.z - mu) * inv * g0.z + b0.z,
                                   (v0.w - mu) * inv * g0.w + b0.w);
    __half2 h2 = __floats2half2_rn((v1.x - mu) * inv * g1.x + b1.x,
                                   (v1.y - mu) * inv * g1.y + b1.y);
    __half2 h3 = __floats2half2_rn((v1.z - mu) * inv * g1.z + b1.z,
                                   (v1.w - mu) * inv * g1.w + b1.w);
    __half* op = out + (size_t)warp * DIM;
    ((uint2*)op)[lane]         = make_uint2(*(uint32_t*)&h0, *(uint32_t*)&h1);
    ((uint2*)(op + 128))[lane] = make_uint2(*(uint32_t*)&h2, *(uint32_t*)&h3);
}

// ---------------- fp16 mma.sync GEMM, 128x128 tile, K-chunk 32, 4-stage ring --
#define HSTR 40
#define HSTAGE (128 * HSTR)                 // halves per matrix per stage
#define STG    (2 * HSTAGE)                 // halves per stage (A+B)
#define GSM_TOTAL (4 * STG * 2)             // 81920 bytes

template<int EPI, typename OT>
__global__ __launch_bounds__(256, 2)
void tc_gemm(const __half* __restrict__ A, const __half* __restrict__ Bt,
             OT* __restrict__ C, int K, int N,
             const float* __restrict__ bias, const float* __restrict__ res) {
    extern __shared__ __half smh[];
    int tid = threadIdx.x;
    int lane = tid & 31, wid = tid >> 5;
    int warp_m = wid & 3;
    int warp_n = wid >> 2;
    int block_row = blockIdx.y * 128;
    int block_col = blockIdx.x * 128;

    const __half* gA = A  + (size_t)block_row * K;
    const __half* gB = Bt + (size_t)block_col * K;

    auto stage = [&](int c) {
        int s = c & 3;
        int c0 = c * 32;
        uint32_t smA = smem_u32(smh + (size_t)s * STG);
        uint32_t smB = smA + HSTAGE * 2;
        #pragma unroll
        for (int it = 0; it < 2; ++it) {
            int seg = tid + it * 256;
            int r = seg >> 2, sg = (seg & 3) * 8;
            cp_async16(smA + (uint32_t)(r * HSTR + sg) * 2,
                       gA + (size_t)r * K + c0 + sg);
        }
        #pragma unroll
        for (int it = 0; it < 2; ++it) {
            int seg = tid + it * 256;
            int r = seg >> 2, sg = (seg & 3) * 8;
            cp_async16(smB + (uint32_t)(r * HSTR + sg) * 2,
                       gB + (size_t)r * K + c0 + sg);
        }
        asm volatile("cp.async.commit_group;");
    };

    float acc[2][8][4];
    #pragma unroll
    for (int i = 0; i < 2; i++)
        #pragma unroll
        for (int j = 0; j < 8; j++)
            #pragma unroll
            for (int q = 0; q < 4; q++) acc[i][j][q] = 0.0f;

    const int nch = K >> 5;
    stage(0);
    if (nch > 1) stage(1);

    int ldm_row  = lane & 7;
    int ldm_tile = lane >> 3;
    int a_roff = warp_m * 32 + (ldm_tile & 1) * 8 + ldm_row;
    int a_coff = (ldm_tile >> 1) * 8;
    int b_roff = warp_n * 64 + (ldm_tile >> 1) * 8 + ldm_row;
    int b_coff = (ldm_tile & 1) * 8;

    for (int c = 0; c < nch; ++c) {
        if (c + 2 < nch) {
            stage(c + 2);
            asm volatile("cp.async.wait_group 2;");
        } else if (c + 1 < nch) {
            asm volatile("cp.async.wait_group 1;");
        } else {
            asm volatile("cp.async.wait_group 0;");
        }
        __syncthreads();
        // NOTE: no trailing barrier — 4-stage ring with prefetch distance 2
        // guarantees stage(c+2) writes a buffer last read at iter c-2, ordered
        // by the top barrier of iter c-1.
        int s = c & 3;
        uint32_t As = smem_u32(smh + (size_t)s * STG);
        uint32_t Bs = As + HSTAGE * 2;
        #pragma unroll
        for (int kk = 0; kk < 32; kk += 16) {
            uint32_t a[2][4];
            #pragma unroll
            for (int am = 0; am < 2; ++am)
                ldm_x4(a[am], As + (uint32_t)((a_roff + am * 16) * HSTR + kk + a_coff) * 2);
            uint32_t b[4][4];
            #pragma unroll
            for (int bp = 0; bp < 4; ++bp)
                ldm_x4(b[bp], Bs + (uint32_t)((b_roff + bp * 16) * HSTR + kk + b_coff) * 2);
            #pragma unroll
            for (int am = 0; am < 2; ++am)
                #pragma unroll
                for (int bp = 0; bp < 4; ++bp) {
                    mma_f16(acc[am][2 * bp],     a[am], b[bp]);
                    mma_f16(acc[am][2 * bp + 1], a[am], b[bp] + 2);
                }
        }
    }

    #pragma unroll
    for (int am = 0; am < 2; ++am) {
        int row0 = block_row + warp_m * 32 + am * 16 + (lane >> 2);
        #pragma unroll
        for (int bn = 0; bn < 8; ++bn) {
            int col = block_col + warp_n * 64 + bn * 8 + 2 * (lane & 3);
            float2 v0 = make_float2(acc[am][bn][0], acc[am][bn][1]);
            float2 v1 = make_float2(acc[am][bn][2], acc[am][bn][3]);
            if (EPI >= 1) {
                float bx = bias[col], by = bias[col + 1];
                v0.x += bx; v0.y += by; v1.x += bx; v1.y += by;
            }
            if (EPI == 2) {
                v0.x = gelu_exact(v0.x); v0.y = gelu_exact(v0.y);
                v1.x = gelu_exact(v1.x); v1.y = gelu_exact(v1.y);
            }
            if (EPI == 3) {
                const float2 r0 = *(const float2*)&res[(size_t)row0 * N + col];
                const float2 r1 = *(const float2*)&res[(size_t)(row0 + 8) * N + col];
                v0.x += r0.x; v0.y += r0.y; v1.x += r1.x; v1.y += r1.y;
            }
            if constexpr (sizeof(OT) == 2) {
                __half2 h0 = __floats2half2_rn(v0.x, v0.y);
                __half2 h1 = __floats2half2_rn(v1.x, v1.y);
                *(__half2*)&C[(size_t)row0 * N + col]       = h0;
                *(__half2*)&C[(size_t)(row0 + 8) * N + col] = h1;
            } else {
                *(float2*)&C[(size_t)row0 * N + col]       = v0;
                *(float2*)&C[(size_t)(row0 + 8) * N + col] = v1;
            }
        }
    }
}

// ---------------- tensor-core windowed attention --------------------------------
#define QSTR 40
#define BSTR 68

__global__ __launch_bounds__(128)
void attn_kernel(const __half* __restrict__ qkv,
                 const float* __restrict__ gbias,
                 __half* __restrict__ out) {
    __shared__ __half sQ[64][QSTR];
    __shared__ __half sK[64][QSTR];
    __shared__ __half sV[64][QSTR];
    __shared__ float  sB[64][BSTR];

    int wi = blockIdx.x;
    int h  = blockIdx.y;
    int tid = threadIdx.x;
    int lane = tid & 31, w = tid >> 5;

    int b = wi >> 6, wrem = wi & 63;
    int wh = wrem >> 3, ww = wrem & 7;
    int tok_row = b * 4096 + wh * 8 * 64 + ww * 8;

    {
        int t = tid >> 1;
        int part = (tid & 1) * 16;
        int gt = tok_row + (t >> 3) * 64 + (t & 7);
        const __half* src = qkv + (size_t)gt * QKVC + h * 32 + part;
        *(uint4*)&sQ[t][part]     = *(const uint4*)(src);
        *(uint4*)&sQ[t][part + 8] = *(const uint4*)(src + 8);
        *(uint4*)&sK[t][part]     = *(const uint4*)(src + 256);
        *(uint4*)&sK[t][part + 8] = *(const uint4*)(src + 264);
        *(uint4*)&sV[t][part]     = *(const uint4*)(src + 512);
        *(uint4*)&sV[t][part + 8] = *(const uint4*)(src + 520);
    }
    {
        const float* gb = gbias + h * 4096;
        #pragma unroll
        for (int it = 0; it < 8; ++it) {
            int i4 = tid + it * 128;
            int r = i4 >> 4, c4 = (i4 & 15) * 4;
            *(float4*)&sB[r][c4] = *(const float4*)&gb[r * 64 + c4];
        }
    }
    __syncthreads();

    int r0 = w * 16;
    int quad = lane >> 2, tq = lane & 3;
    int r_lo = r0 + quad;
    int ldm_row = lane & 7;
    int ldm_tile = lane >> 3;

    float sacc[8][4];
    #pragma unroll
    for (int a = 0; a < 8; a++)
        #pragma unroll
        for (int q = 0; q < 4; q++) sacc[a][q] = 0.0f;

    #pragma unroll
    for (int kt = 0; kt < 2; ++kt) {
        int k0 = kt * 16;
        uint32_t af[4];
        ldm_x4(af, smem_u32(&sQ[r0 + (ldm_tile & 1) * 8 + ldm_row]
                              [k0 + (ldm_tile >> 1) * 8]));
        #pragma unroll
        for (int ap = 0; ap < 4; ++ap) {
            int n0 = ap * 16;
            uint32_t bf[4];
            ldm_x4(bf, smem_u32(&sK[n0 + (ldm_tile >> 1) * 8 + ldm_row]
                                  [k0 + (ldm_tile & 1) * 8]));
            mma_f16(sacc[2 * ap],     af, bf);
            mma_f16(sacc[2 * ap + 1], af, bf + 2);
        }
    }

    const float scale = 0.17677669529663688f;
    float mx_lo = -1e30f, mx_hi = -1e30f;
    #pragma unroll
    for (int a = 0; a < 8; ++a) {
        int c0 = a * 8 + 2 * tq;
        sacc[a][0] = sacc[a][0] * scale + sB[r_lo][c0];
        sacc[a][1] = sacc[a][1] * scale + sB[r_lo][c0 + 1];
        sacc[a][2] = sacc[a][2] * scale + sB[r_lo + 8][c0];
        sacc[a][3] = sacc[a][3] * scale + sB[r_lo + 8][c0 + 1];
        mx_lo = fmaxf(mx_lo, fmaxf(sacc[a][0], sacc[a][1]));
        mx_hi = fmaxf(mx_hi, fmaxf(sacc[a][2], sacc[a][3]));
    }
    #pragma unroll
    for (int o = 1; o <= 2; o <<= 1) {
        mx_lo = fmaxf(mx_lo, __shfl_xor_sync(0xffffffffu, mx_lo, o));
        mx_hi = fmaxf(mx_hi, __shfl_xor_sync(0xffffffffu, mx_hi, o));
    }
    float sum_lo = 0.0f, sum_hi = 0.0f;
    #pragma unroll
    for (int a = 0; a < 8; ++a) {
        sacc[a][0] = __expf(sacc[a][0] - mx_lo);
        sacc[a][1] = __expf(sacc[a][1] - mx_lo);
        sacc[a][2] = __expf(sacc[a][2] - mx_hi);
        sacc[a][3] = __expf(sacc[a][3] - mx_hi);
        sum_lo += sacc[a][0] + sacc[a][1];
        sum_hi += sacc[a][2] + sacc[a][3];
    }
    #pragma unroll
    for (int o = 1; o <= 2; o <<= 1) {
        sum_lo += __shfl_xor_sync(0xffffffffu, sum_lo, o);
        sum_hi += __shfl_xor_sync(0xffffffffu, sum_hi, o);
    }

    float oacc[4][4];
    #pragma unroll
    for (int a = 0; a < 4; a++)
        #pragma unroll
        for (int q = 0; q < 4; q++) oacc[a][q] = 0.0f;

    #pragma unroll
    for (int kt = 0; kt < 4; ++kt) {
        uint32_t ap_[4];
        ap_[0] = pack_h2(sacc[2*kt][0],     sacc[2*kt][1]);
        ap_[1] = pack_h2(sacc[2*kt][2],     sacc[2*kt][3]);
        ap_[2] = pack_h2(sacc[2*kt+1][0],   sacc[2*kt+1][1]);
        ap_[3] = pack_h2(sacc[2*kt+1][2],   sacc[2*kt+1][3]);
        int k0 = kt * 16;
        #pragma unroll
        for (int np = 0; np < 2; ++np) {
            int n0 = np * 16;
            uint32_t bf[4];
            ldm_x4_t(bf, smem_u32(&sV[k0 + (ldm_tile & 1) * 8 + ldm_row]
                                    [n0 + (ldm_tile >> 1) * 8]));
            mma_f16(oacc[2 * np],     ap_, bf);
            mma_f16(oacc[2 * np + 1], ap_, bf + 2);
        }
    }

    float inv_lo = 1.0f / sum_lo, inv_hi = 1.0f / sum_hi;
    int gt_lo = tok_row + (r_lo >> 3) * 64 + (r_lo & 7);
    int r_hi = r_lo + 8;
    int gt_hi = tok_row + (r_hi >> 3) * 64 + (r_hi & 7);
    #pragma unroll
    for (int a = 0; a < 4; ++a) {
        int col = h * 32 + a * 8 + 2 * tq;
        __half2 lo = __floats2half2_rn(oacc[a][0] * inv_lo, oacc[a][1] * inv_lo);
        __half2 hi = __floats2half2_rn(oacc[a][2] * inv_hi, oacc[a][3] * inv_hi);
        *(__half2*)&out[(size_t)gt_lo * DIM + col] = lo;
        *(__half2*)&out[(size_t)gt_hi * DIM + col] = hi;
    }
}

// ---------------- launch ------------------------------------------------------
extern "C" void kernel_launch(void* const* d_in, const int* in_sizes, int n_in,
                              void* d_out, int out_size) {
    const float* x      = (const float*)d_in[0];
    const float* ln1_g  = (const float*)d_in[3];
    const float* ln1_b  = (const float*)d_in[4];
    const float* qkv_w  = (const float*)d_in[5];
    const float* proj_w = (const float*)d_in[6];
    const float* proj_b = (const float*)d_in[7];
    const float* relb   = (const float*)d_in[8];
    const float* ln2_g  = (const float*)d_in[9];
    const float* ln2_b  = (const float*)d_in[10];
    const float* fc1_w  = (const float*)d_in[11];
    const float* fc1_b  = (const float*)d_in[12];
    const float* fc2_w  = (const float*)d_in[13];
    const float* fc2_b  = (const float*)d_in[14];
    float* out = (float*)d_out;

    __half *p_lnh, *p_qkvh, *p_attnh, *p_mlph, *p_wth;
    float  *p_bias;
    cudaGetSymbolAddress((void**)&p_lnh,   g_lnh);
    cudaGetSymbolAddress((void**)&p_qkvh,  g_qkvh);
    cudaGetSymbolAddress((void**)&p_attnh, g_attnh);
    cudaGetSymbolAddress((void**)&p_mlph,  g_mlph);
    cudaGetSymbolAddress((void**)&p_wth,   g_wth);
    cudaGetSymbolAddress((void**)&p_bias,  g_bias);

    cudaFuncSetAttribute((const void*)tc_gemm<0, __half>, cudaFuncAttributeMaxDynamicSharedMemorySize, GSM_TOTAL);
    cudaFuncSetAttribute((const void*)tc_gemm<2, __half>, cudaFuncAttributeMaxDynamicSharedMemorySize, GSM_TOTAL);
    cudaFuncSetAttribute((const void*)tc_gemm<3, float >, cudaFuncAttributeMaxDynamicSharedMemorySize, GSM_TOTAL);

    // 0. fused prep: weight transposes + bias table (one launch)
    prep_kernel<<<776, dim3(32, 8)>>>(qkv_w, proj_w, fc1_w, fc2_w, relb, p_wth, p_bias);
    // 1. LN1 -> half
    ln_kernel<<<NTOK / 8, 256>>>(x, ln1_g, ln1_b, p_lnh);
    // 2. QKV -> half
    tc_gemm<0, __half><<<dim3(QKVC / 128, NTOK / 128), 256, GSM_TOTAL>>>(
        p_lnh, p_wth + WT_QKV, p_qkvh, DIM, QKVC, nullptr, nullptr);
    // 3. tensor-core window attention -> half
    attn_kernel<<<dim3(1024, 8), 128>>>(p_qkvh, p_bias, p_attnh);
    // 4. proj + bias + residual(x) -> out fp32
    tc_gemm<3, float><<<dim3(DIM / 128, NTOK / 128), 256, GSM_TOTAL>>>(
        p_attnh, p_wth + WT_PROJ, out, DIM, DIM, proj_b, x);
    // 5. LN2 -> half
    ln_kernel<<<NTOK / 8, 256>>>(out, ln2_g, ln2_b, p_lnh);
    // 6. fc1 + bias + gelu -> half
    tc_gemm<2, __half><<<dim3(HID / 128, NTOK / 128), 256, GSM_TOTAL>>>(
        p_lnh, p_wth + WT_FC1, p_mlph, DIM, HID, fc1_b, nullptr);
    // 7. fc2 + bias + residual(out) -> out fp32
    tc_gemm<3, float><<<dim3(DIM / 128, NTOK / 128), 256, GSM_TOTAL>>>(
        p_mlph, p_wth + WT_FC2, out, HID, DIM, fc2_b, out);
}

// round 10
// speedup vs baseline: 2.0862x; 1.0368x over previous
#include <cuda_runtime.h>
#include <cuda_fp16.h>
#include <math.h>
#include <stdint.h>

#define NTOK 65536            // 16 * 4096
#define DIM 256
#define QKVC 768
#define HID 1024

// ---------------- scratch ----------------------------------------------------
__device__ __half g_lnh  [(size_t)NTOK * DIM];
__device__ __half g_qkvh [(size_t)NTOK * QKVC];
__device__ __half g_attnh[(size_t)NTOK * DIM];
__device__ __half g_mlph [(size_t)NTOK * HID];
__device__ __half g_biash[8 * 64 * 64];          // per-head rel-pos bias (half)
#define WT_QKV 0
#define WT_PROJ (QKVC * DIM)
#define WT_FC1  (WT_PROJ + DIM * DIM)
#define WT_FC2  (WT_FC1 + HID * DIM)
__device__ __half g_wth[WT_FC2 + DIM * HID];

// ---------------- helpers -----------------------------------------------------
__device__ __forceinline__ uint32_t smem_u32(const void* p) {
    return (uint32_t)__cvta_generic_to_shared((void*)p);
}
__device__ __forceinline__ void cp_async16(uint32_t dst, const void* src) {
    asm volatile("cp.async.cg.shared.global [%0], [%1], 16;" :: "r"(dst), "l"(src));
}
__device__ __forceinline__ float gelu_exact(float v) {
    return 0.5f * v * (1.0f + erff(v * 0.70710678118654752f));
}
__device__ __forceinline__ void mma_f16(float* c, const uint32_t* a, const uint32_t* b) {
    asm volatile(
        "mma.sync.aligned.m16n8k16.row.col.f32.f16.f16.f32 "
        "{%0,%1,%2,%3}, {%4,%5,%6,%7}, {%8,%9}, {%0,%1,%2,%3};"
        : "+f"(c[0]), "+f"(c[1]), "+f"(c[2]), "+f"(c[3])
        : "r"(a[0]), "r"(a[1]), "r"(a[2]), "r"(a[3]), "r"(b[0]), "r"(b[1]));
}
__device__ __forceinline__ void ldm_x4(uint32_t* r, uint32_t addr) {
    asm volatile("ldmatrix.sync.aligned.m8n8.x4.shared.b16 {%0,%1,%2,%3}, [%4];"
                 : "=r"(r[0]), "=r"(r[1]), "=r"(r[2]), "=r"(r[3]) : "r"(addr));
}
__device__ __forceinline__ void ldm_x4_t(uint32_t* r, uint32_t addr) {
    asm volatile("ldmatrix.sync.aligned.m8n8.x4.trans.shared.b16 {%0,%1,%2,%3}, [%4];"
                 : "=r"(r[0]), "=r"(r[1]), "=r"(r[2]), "=r"(r[3]) : "r"(addr));
}
__device__ __forceinline__ uint32_t pack_h2(float a, float b) {
    __half2 h = __floats2half2_rn(a, b);
    return *(uint32_t*)&h;
}
__device__ __forceinline__ float2 h2f2(uint32_t u) {
    return __half22float2(*(__half2*)&u);
}

// ---------------- fused prep: 4 weight transposes + bias table ----------------
// blocks 0..191 QKV, 192..255 proj, 256..511 fc1, 512..767 fc2, 768..775 bias
__global__ void prep_kernel(const float* __restrict__ qkv_w,
                            const float* __restrict__ proj_w,
                            const float* __restrict__ fc1_w,
                            const float* __restrict__ fc2_w,
                            const float* __restrict__ relb,
                            __half* __restrict__ wt, __half* __restrict__ gb) {
    int blk = blockIdx.x;
    int x = threadIdx.x, y = threadIdx.y;
    if (blk >= 768) {            // bias table (half)
        int h = blk - 768;
        int tid = y * 32 + x;
        #pragma unroll
        for (int it = 0; it < 16; ++it) {
            int e = tid + it * 256;       // 0..4095
            int i = e >> 6, j = e & 63;
            int ridx = ((i >> 3) - (j >> 3) + 7) * 15 + ((i & 7) - (j & 7) + 7);
            gb[h * 4096 + e] = __float2half(relb[ridx * 8 + h]);
        }
        return;
    }
    const float* in; __half* out; int R, C, bx, by;
    if (blk < 192)      { in = qkv_w;  out = wt + WT_QKV;  R = DIM; C = QKVC;
                          int i = blk;       bx = (i % 24) * 32; by = (i / 24) * 32; }
    else if (blk < 256) { in = proj_w; out = wt + WT_PROJ; R = DIM; C = DIM;
                          int i = blk - 192; bx = (i % 8) * 32;  by = (i / 8) * 32; }
    else if (blk < 512) { in = fc1_w;  out = wt + WT_FC1;  R = DIM; C = HID;
                          int i = blk - 256; bx = (i % 32) * 32; by = (i / 32) * 32; }
    else                { in = fc2_w;  out = wt + WT_FC2;  R = HID; C = DIM;
                          int i = blk - 512; bx = (i % 8) * 32;  by = (i / 8) * 32; }
    __shared__ float t[32][33];
    #pragma unroll
    for (int j = 0; j < 32; j += 8)
        t[y + j][x] = in[(size_t)(by + y + j) * C + bx + x];
    __syncthreads();
    #pragma unroll
    for (int j = 0; j < 32; j += 8)
        out[(size_t)(bx + y + j) * R + by + x] = __float2half(t[x][y + j]);
}

// ---------------- LayerNorm: one warp per token, fp32 in -> fp16 out ----------
__global__ void ln_kernel(const float* __restrict__ x,
                          const float* __restrict__ g,
                          const float* __restrict__ b,
                          __half* __restrict__ out) {
    int warp = (blockIdx.x * blockDim.x + threadIdx.x) >> 5;
    int lane = threadIdx.x & 31;
    if (warp >= NTOK) return;
    const float* xp = x + (size_t)warp * DIM;
    float4 v0 = *(const float4*)(xp + lane * 4);
    float4 v1 = *(const float4*)(xp + 128 + lane * 4);
    float s  = v0.x + v0.y + v0.z + v0.w + v1.x + v1.y + v1.z + v1.w;
    float ss = v0.x*v0.x + v0.y*v0.y + v0.z*v0.z + v0.w*v0.w
             + v1.x*v1.x + v1.y*v1.y + v1.z*v1.z + v1.w*v1.w;
    #pragma unroll
    for (int o = 16; o > 0; o >>= 1) {
        s  += __shfl_xor_sync(0xffffffffu, s,  o);
        ss += __shfl_xor_sync(0xffffffffu, ss, o);
    }
    float mu  = s * (1.0f / DIM);
    float var = ss * (1.0f / DIM) - mu * mu;
    float inv = rsqrtf(var + 1e-5f);
    float4 g0 = *(const float4*)(g + lane * 4);
    float4 g1 = *(const float4*)(g + 128 + lane * 4);
    float4 b0 = *(const float4*)(b + lane * 4);
    float4 b1 = *(const float4*)(b + 128 + lane * 4);
    __half2 h0 = __floats2half2_rn((v0.x - mu) * inv * g0.x + b0.x,
                                   (v0.y - mu) * inv * g0.y + b0.y);
    __half2 h1 = __floats2half2_rn((v0.z - mu) * inv * g0.z + b0.z,
                                   (v0.w - mu) * inv * g0.w + b0.w);
    __half2 h2 = __floats2half2_rn((v1.x - mu) * inv * g1.x + b1.x,
                                   (v1.y - mu) * inv * g1.y + b1.y);
    __half2 h3 = __floats2half2_rn((v1.z - mu) * inv * g1.z + b1.z,
                                   (v1.w - mu) * inv * g1.w + b1.w);
    __half* op = out + (size_t)warp * DIM;
    ((uint2*)op)[lane]         = make_uint2(*(uint32_t*)&h0, *(uint32_t*)&h1);
    ((uint2*)(op + 128))[lane] = make_uint2(*(uint32_t*)&h2, *(uint32_t*)&h3);
}

// ---------------- fp16 mma.sync GEMM, 128x128 tile, K-chunk 32, 4-stage ring --
#define HSTR 40
#define HSTAGE (128 * HSTR)
#define STG    (2 * HSTAGE)
#define GSM_TOTAL (4 * STG * 2)             // 81920 bytes

template<int EPI, typename OT>
__global__ __launch_bounds__(256, 2)
void tc_gemm(const __half* __restrict__ A, const __half* __restrict__ Bt,
             OT* __restrict__ C, int K, int N,
             const float* __restrict__ bias, const float* __restrict__ res) {
    extern __shared__ __half smh[];
    int tid = threadIdx.x;
    int lane = tid & 31, wid = tid >> 5;
    int warp_m = wid & 3;
    int warp_n = wid >> 2;
    int block_row = blockIdx.y * 128;
    int block_col = blockIdx.x * 128;

    const __half* gA = A  + (size_t)block_row * K;
    const __half* gB = Bt + (size_t)block_col * K;

    auto stage = [&](int c) {
        int s = c & 3;
        int c0 = c * 32;
        uint32_t smA = smem_u32(smh + (size_t)s * STG);
        uint32_t smB = smA + HSTAGE * 2;
        #pragma unroll
        for (int it = 0; it < 2; ++it) {
            int seg = tid + it * 256;
            int r = seg >> 2, sg = (seg & 3) * 8;
            cp_async16(smA + (uint32_t)(r * HSTR + sg) * 2,
                       gA + (size_t)r * K + c0 + sg);
        }
        #pragma unroll
        for (int it = 0; it < 2; ++it) {
            int seg = tid + it * 256;
            int r = seg >> 2, sg = (seg & 3) * 8;
            cp_async16(smB + (uint32_t)(r * HSTR + sg) * 2,
                       gB + (size_t)r * K + c0 + sg);
        }
        asm volatile("cp.async.commit_group;");
    };

    float acc[2][8][4];
    #pragma unroll
    for (int i = 0; i < 2; i++)
        #pragma unroll
        for (int j = 0; j < 8; j++)
            #pragma unroll
            for (int q = 0; q < 4; q++) acc[i][j][q] = 0.0f;

    const int nch = K >> 5;
    stage(0);
    if (nch > 1) stage(1);

    int ldm_row  = lane & 7;
    int ldm_tile = lane >> 3;
    int a_roff = warp_m * 32 + (ldm_tile & 1) * 8 + ldm_row;
    int a_coff = (ldm_tile >> 1) * 8;
    int b_roff = warp_n * 64 + (ldm_tile >> 1) * 8 + ldm_row;
    int b_coff = (ldm_tile & 1) * 8;

    for (int c = 0; c < nch; ++c) {
        if (c + 2 < nch) {
            stage(c + 2);
            asm volatile("cp.async.wait_group 2;");
        } else if (c + 1 < nch) {
            asm volatile("cp.async.wait_group 1;");
        } else {
            asm volatile("cp.async.wait_group 0;");
        }
        __syncthreads();
        int s = c & 3;
        uint32_t As = smem_u32(smh + (size_t)s * STG);
        uint32_t Bs = As + HSTAGE * 2;
        #pragma unroll
        for (int kk = 0; kk < 32; kk += 16) {
            uint32_t a[2][4];
            #pragma unroll
            for (int am = 0; am < 2; ++am)
                ldm_x4(a[am], As + (uint32_t)((a_roff + am * 16) * HSTR + kk + a_coff) * 2);
            uint32_t b[4][4];
            #pragma unroll
            for (int bp = 0; bp < 4; ++bp)
                ldm_x4(b[bp], Bs + (uint32_t)((b_roff + bp * 16) * HSTR + kk + b_coff) * 2);
            #pragma unroll
            for (int am = 0; am < 2; ++am)
                #pragma unroll
                for (int bp = 0; bp < 4; ++bp) {
                    mma_f16(acc[am][2 * bp],     a[am], b[bp]);
                    mma_f16(acc[am][2 * bp + 1], a[am], b[bp] + 2);
                }
        }
    }

    #pragma unroll
    for (int am = 0; am < 2; ++am) {
        int row0 = block_row + warp_m * 32 + am * 16 + (lane >> 2);
        #pragma unroll
        for (int bn = 0; bn < 8; ++bn) {
            int col = block_col + warp_n * 64 + bn * 8 + 2 * (lane & 3);
            float2 v0 = make_float2(acc[am][bn][0], acc[am][bn][1]);
            float2 v1 = make_float2(acc[am][bn][2], acc[am][bn][3]);
            if (EPI >= 1) {
                float bx = bias[col], by = bias[col + 1];
                v0.x += bx; v0.y += by; v1.x += bx; v1.y += by;
            }
            if (EPI == 2) {
                v0.x = gelu_exact(v0.x); v0.y = gelu_exact(v0.y);
                v1.x = gelu_exact(v1.x); v1.y = gelu_exact(v1.y);
            }
            if (EPI == 3) {
                const float2 r0 = *(const float2*)&res[(size_t)row0 * N + col];
                const float2 r1 = *(const float2*)&res[(size_t)(row0 + 8) * N + col];
                v0.x += r0.x; v0.y += r0.y; v1.x += r1.x; v1.y += r1.y;
            }
            if constexpr (sizeof(OT) == 2) {
                __half2 h0 = __floats2half2_rn(v0.x, v0.y);
                __half2 h1 = __floats2half2_rn(v1.x, v1.y);
                *(__half2*)&C[(size_t)row0 * N + col]       = h0;
                *(__half2*)&C[(size_t)(row0 + 8) * N + col] = h1;
            } else {
                *(float2*)&C[(size_t)row0 * N + col]       = v0;
                *(float2*)&C[(size_t)(row0 + 8) * N + col] = v1;
            }
        }
    }
}

// ---------------- tensor-core windowed attention, 2 windows/block --------------
// block = (window pair, head), 256 threads / 8 warps; warps 0-3 -> window 0,
// warps 4-7 -> window 1. Bias tile (half) shared by both windows, added via
// ldmatrix fragments (C-fragment layout == ldmatrix b16 layout).
#define QSTR 40   // halves per SMEM row for Q/K/V
#define BSTR 72   // halves per SMEM row for bias

__global__ __launch_bounds__(256)
void attn_kernel(const __half* __restrict__ qkv,
                 const __half* __restrict__ gbias,
                 __half* __restrict__ out) {
    __shared__ __half sQ[2][64][QSTR];
    __shared__ __half sK[2][64][QSTR];
    __shared__ __half sV[2][64][QSTR];
    __shared__ __half sB[64][BSTR];

    int h  = blockIdx.y;
    int tid = threadIdx.x;
    int lane = tid & 31, w = tid >> 5;
    int widx = w >> 2;           // window within pair (compute role)
    int wl   = w & 3;            // warp within window

    // token base for each window of the pair
    int wi0 = blockIdx.x * 2;
    int tok_row_arr[2];
    #pragma unroll
    for (int v = 0; v < 2; ++v) {
        int wi = wi0 + v;
        int b = wi >> 6, wrem = wi & 63;
        tok_row_arr[v] = b * 4096 + (wrem >> 3) * 8 * 64 + (wrem & 7) * 8;
    }

    // load Q/K/V: threads 0-127 -> window 0, 128-255 -> window 1
    {
        int lv = tid >> 7;               // load window
        int t2 = tid & 127;
        int t = t2 >> 1;
        int part = (t2 & 1) * 16;
        int gt = tok_row_arr[lv] + (t >> 3) * 64 + (t & 7);
        const __half* src = qkv + (size_t)gt * QKVC + h * 32 + part;
        *(uint4*)&sQ[lv][t][part]     = *(const uint4*)(src);
        *(uint4*)&sQ[lv][t][part + 8] = *(const uint4*)(src + 8);
        *(uint4*)&sK[lv][t][part]     = *(const uint4*)(src + 256);
        *(uint4*)&sK[lv][t][part + 8] = *(const uint4*)(src + 264);
        *(uint4*)&sV[lv][t][part]     = *(const uint4*)(src + 512);
        *(uint4*)&sV[lv][t][part + 8] = *(const uint4*)(src + 520);
    }
    // load bias tile (64x64 half = 512 uint4), once for both windows
    {
        const __half* gb = gbias + h * 4096;
        #pragma unroll
        for (int it = 0; it < 2; ++it) {
            int i8 = tid + it * 256;     // uint4 index 0..511
            int r = i8 >> 3, c8 = (i8 & 7) * 8;
            *(uint4*)&sB[r][c8] = *(const uint4*)&gb[r * 64 + c8];
        }
    }
    __syncthreads();

    int r0 = wl * 16;
    int quad = lane >> 2, tq = lane & 3;
    int r_lo = r0 + quad;
    int ldm_row = lane & 7;
    int ldm_tile = lane >> 3;

    // ---- S = Q K^T ----
    float sacc[8][4];
    #pragma unroll
    for (int a = 0; a < 8; a++)
        #pragma unroll
        for (int q = 0; q < 4; q++) sacc[a][q] = 0.0f;

    #pragma unroll
    for (int kt = 0; kt < 2; ++kt) {
        int k0 = kt * 16;
        uint32_t af[4];
        ldm_x4(af, smem_u32(&sQ[widx][r0 + (ldm_tile & 1) * 8 + ldm_row]
                               [k0 + (ldm_tile >> 1) * 8]));
        #pragma unroll
        for (int ap = 0; ap < 4; ++ap) {
            int n0 = ap * 16;
            uint32_t bf[4];
            ldm_x4(bf, smem_u32(&sK[widx][n0 + (ldm_tile >> 1) * 8 + ldm_row]
                                   [k0 + (ldm_tile & 1) * 8]));
            mma_f16(sacc[2 * ap],     af, bf);
            mma_f16(sacc[2 * ap + 1], af, bf + 2);
        }
    }

    // ---- scale + bias (ldmatrix fragments) + softmax ----
    const float scale = 0.17677669529663688f;
    float mx_lo = -1e30f, mx_hi = -1e30f;
    #pragma unroll
    for (int j = 0; j < 4; ++j) {        // 16x16 bias tiles along columns
        uint32_t bfr[4];
        ldm_x4(bfr, smem_u32(&sB[r0 + (ldm_tile & 1) * 8 + ldm_row]
                               [16 * j + (ldm_tile >> 1) * 8]));
        float2 b0 = h2f2(bfr[0]);        // rows quad,   cols 16j+2tq..
        float2 b1 = h2f2(bfr[1]);        // rows quad+8
        float2 b2 = h2f2(bfr[2]);        // rows quad,   cols +8
        float2 b3 = h2f2(bfr[3]);        // rows quad+8, cols +8
        int a0 = 2 * j, a1 = 2 * j + 1;
        sacc[a0][0] = fmaf(sacc[a0][0], scale, b0.x);
        sacc[a0][1] = fmaf(sacc[a0][1], scale, b0.y);
        sacc[a0][2] = fmaf(sacc[a0][2], scale, b1.x);
        sacc[a0][3] = fmaf(sacc[a0][3], scale, b1.y);
        sacc[a1][0] = fmaf(sacc[a1][0], scale, b2.x);
        sacc[a1][1] = fmaf(sacc[a1][1], scale, b2.y);
        sacc[a1][2] = fmaf(sacc[a1][2], scale, b3.x);
        sacc[a1][3] = fmaf(sacc[a1][3], scale, b3.y);
    }
    #pragma unroll
    for (int a = 0; a < 8; ++a) {
        mx_lo = fmaxf(mx_lo, fmaxf(sacc[a][0], sacc[a][1]));
        mx_hi = fmaxf(mx_hi, fmaxf(sacc[a][2], sacc[a][3]));
    }
    #pragma unroll
    for (int o = 1; o <= 2; o <<= 1) {
        mx_lo = fmaxf(mx_lo, __shfl_xor_sync(0xffffffffu, mx_lo, o));
        mx_hi = fmaxf(mx_hi, __shfl_xor_sync(0xffffffffu, mx_hi, o));
    }
    float sum_lo = 0.0f, sum_hi = 0.0f;
    #pragma unroll
    for (int a = 0; a < 8; ++a) {
        sacc[a][0] = __expf(sacc[a][0] - mx_lo);
        sacc[a][1] = __expf(sacc[a][1] - mx_lo);
        sacc[a][2] = __expf(sacc[a][2] - mx_hi);
        sacc[a][3] = __expf(sacc[a][3] - mx_hi);
        sum_lo += sacc[a][0] + sacc[a][1];
        sum_hi += sacc[a][2] + sacc[a][3];
    }
    #pragma unroll
    for (int o = 1; o <= 2; o <<= 1) {
        sum_lo += __shfl_xor_sync(0xffffffffu, sum_lo, o);
        sum_hi += __shfl_xor_sync(0xffffffffu, sum_hi, o);
    }

    // ---- O = P V ----
    float oacc[4][4];
    #pragma unroll
    for (int a = 0; a < 4; a++)
        #pragma unroll
        for (int q = 0; q < 4; q++) oacc[a][q] = 0.0f;

    #pragma unroll
    for (int kt = 0; kt < 4; ++kt) {
        uint32_t ap_[4];
        ap_[0] = pack_h2(sacc[2*kt][0],     sacc[2*kt][1]);
        ap_[1] = pack_h2(sacc[2*kt][2],     sacc[2*kt][3]);
        ap_[2] = pack_h2(sacc[2*kt+1][0],   sacc[2*kt+1][1]);
        ap_[3] = pack_h2(sacc[2*kt+1][2],   sacc[2*kt+1][3]);
        int k0 = kt * 16;
        #pragma unroll
        for (int np = 0; np < 2; ++np) {
            int n0 = np * 16;
            uint32_t bf[4];
            ldm_x4_t(bf, smem_u32(&sV[widx][k0 + (ldm_tile & 1) * 8 + ldm_row]
                                     [n0 + (ldm_tile >> 1) * 8]));
            mma_f16(oacc[2 * np],     ap_, bf);
            mma_f16(oacc[2 * np + 1], ap_, bf + 2);
        }
    }

    // ---- normalize + store ----
    float inv_lo = 1.0f / sum_lo, inv_hi = 1.0f / sum_hi;
    int tok_row = tok_row_arr[widx];
    int gt_lo = tok_row + (r_lo >> 3) * 64 + (r_lo & 7);
    int r_hi = r_lo + 8;
    int gt_hi = tok_row + (r_hi >> 3) * 64 + (r_hi & 7);
    #pragma unroll
    for (int a = 0; a < 4; ++a) {
        int col = h * 32 + a * 8 + 2 * tq;
        __half2 lo = __floats2half2_rn(oacc[a][0] * inv_lo, oacc[a][1] * inv_lo);
        __half2 hi = __floats2half2_rn(oacc[a][2] * inv_hi, oacc[a][3] * inv_hi);
        *(__half2*)&out[(size_t)gt_lo * DIM + col] = lo;
        *(__half2*)&out[(size_t)gt_hi * DIM + col] = hi;
    }
}

// ---------------- launch ------------------------------------------------------
extern "C" void kernel_launch(void* const* d_in, const int* in_sizes, int n_in,
                              void* d_out, int out_size) {
    const float* x      = (const float*)d_in[0];
    const float* ln1_g  = (const float*)d_in[3];
    const float* ln1_b  = (const float*)d_in[4];
    const float* qkv_w  = (const float*)d_in[5];
    const float* proj_w = (const float*)d_in[6];
    const float* proj_b = (const float*)d_in[7];
    const float* relb   = (const float*)d_in[8];
    const float* ln2_g  = (const float*)d_in[9];
    const float* ln2_b  = (const float*)d_in[10];
    const float* fc1_w  = (const float*)d_in[11];
    const float* fc1_b  = (const float*)d_in[12];
    const float* fc2_w  = (const float*)d_in[13];
    const float* fc2_b  = (const float*)d_in[14];
    float* out = (float*)d_out;

    __half *p_lnh, *p_qkvh, *p_attnh, *p_mlph, *p_wth, *p_biash;
    cudaGetSymbolAddress((void**)&p_lnh,   g_lnh);
    cudaGetSymbolAddress((void**)&p_qkvh,  g_qkvh);
    cudaGetSymbolAddress((void**)&p_attnh, g_attnh);
    cudaGetSymbolAddress((void**)&p_mlph,  g_mlph);
    cudaGetSymbolAddress((void**)&p_wth,   g_wth);
    cudaGetSymbolAddress((void**)&p_biash, g_biash);

    cudaFuncSetAttribute((const void*)tc_gemm<0, __half>, cudaFuncAttributeMaxDynamicSharedMemorySize, GSM_TOTAL);
    cudaFuncSetAttribute((const void*)tc_gemm<2, __half>, cudaFuncAttributeMaxDynamicSharedMemorySize, GSM_TOTAL);
    cudaFuncSetAttribute((const void*)tc_gemm<3, float >, cudaFuncAttributeMaxDynamicSharedMemorySize, GSM_TOTAL);

    // 0. fused prep
    prep_kernel<<<776, dim3(32, 8)>>>(qkv_w, proj_w, fc1_w, fc2_w, relb, p_wth, p_biash);
    // 1. LN1 -> half
    ln_kernel<<<NTOK / 8, 256>>>(x, ln1_g, ln1_b, p_lnh);
    // 2. QKV -> half
    tc_gemm<0, __half><<<dim3(QKVC / 128, NTOK / 128), 256, GSM_TOTAL>>>(
        p_lnh, p_wth + WT_QKV, p_qkvh, DIM, QKVC, nullptr, nullptr);
    // 3. tensor-core window attention (2 windows / block) -> half
    attn_kernel<<<dim3(512, 8), 256>>>(p_qkvh, p_biash, p_attnh);
    // 4. proj + bias + residual(x) -> out fp32
    tc_gemm<3, float><<<dim3(DIM / 128, NTOK / 128), 256, GSM_TOTAL>>>(
        p_attnh, p_wth + WT_PROJ, out, DIM, DIM, proj_b, x);
    // 5. LN2 -> half
    ln_kernel<<<NTOK / 8, 256>>>(out, ln2_g, ln2_b, p_lnh);
    // 6. fc1 + bias + gelu -> half
    tc_gemm<2, __half><<<dim3(HID / 128, NTOK / 128), 256, GSM_TOTAL>>>(
        p_lnh, p_wth + WT_FC1, p_mlph, DIM, HID, fc1_b, nullptr);
    // 7. fc2 + bias + residual(out) -> out fp32
    tc_gemm<3, float><<<dim3(DIM / 128, NTOK / 128), 256, GSM_TOTAL>>>(
        p_mlph, p_wth + WT_FC2, out, HID, DIM, fc2_b, out);
}

// round 11
// speedup vs baseline: 2.0863x; 1.0001x over previous
#include <cuda_runtime.h>
#include <cuda_fp16.h>
#include <math.h>
#include <stdint.h>

#define NTOK 65536            // 16 * 4096
#define DIM 256
#define QKVC 768
#define HID 1024

// ---------------- scratch ----------------------------------------------------
__device__ __half g_lnh  [(size_t)NTOK * DIM];
__device__ __half g_qkvh [(size_t)NTOK * QKVC];
__device__ __half g_attnh[(size_t)NTOK * DIM];
__device__ __half g_mlph [(size_t)NTOK * HID];
__device__ __half g_biash[8 * 64 * 64];
#define WT_QKV 0
#define WT_PROJ (QKVC * DIM)
#define WT_FC1  (WT_PROJ + DIM * DIM)
#define WT_FC2  (WT_FC1 + HID * DIM)
__device__ __half g_wth[WT_FC2 + DIM * HID];

// ---------------- helpers -----------------------------------------------------
__device__ __forceinline__ uint32_t smem_u32(const void* p) {
    return (uint32_t)__cvta_generic_to_shared((void*)p);
}
__device__ __forceinline__ void cp_async16(uint32_t dst, const void* src) {
    asm volatile("cp.async.cg.shared.global [%0], [%1], 16;" :: "r"(dst), "l"(src));
}
__device__ __forceinline__ float gelu_exact(float v) {
    return 0.5f * v * (1.0f + erff(v * 0.70710678118654752f));
}
__device__ __forceinline__ void mma_f16(float* c, const uint32_t* a, const uint32_t* b) {
    asm volatile(
        "mma.sync.aligned.m16n8k16.row.col.f32.f16.f16.f32 "
        "{%0,%1,%2,%3}, {%4,%5,%6,%7}, {%8,%9}, {%0,%1,%2,%3};"
        : "+f"(c[0]), "+f"(c[1]), "+f"(c[2]), "+f"(c[3])
        : "r"(a[0]), "r"(a[1]), "r"(a[2]), "r"(a[3]), "r"(b[0]), "r"(b[1]));
}
__device__ __forceinline__ void ldm_x4(uint32_t* r, uint32_t addr) {
    asm volatile("ldmatrix.sync.aligned.m8n8.x4.shared.b16 {%0,%1,%2,%3}, [%4];"
                 : "=r"(r[0]), "=r"(r[1]), "=r"(r[2]), "=r"(r[3]) : "r"(addr));
}
__device__ __forceinline__ void ldm_x4_t(uint32_t* r, uint32_t addr) {
    asm volatile("ldmatrix.sync.aligned.m8n8.x4.trans.shared.b16 {%0,%1,%2,%3}, [%4];"
                 : "=r"(r[0]), "=r"(r[1]), "=r"(r[2]), "=r"(r[3]) : "r"(addr));
}
__device__ __forceinline__ uint32_t pack_h2(float a, float b) {
    __half2 h = __floats2half2_rn(a, b);
    return *(uint32_t*)&h;
}
__device__ __forceinline__ float2 h2f2(uint32_t u) {
    return __half22float2(*(__half2*)&u);
}

// ---------------- fused prep: 4 weight transposes + bias table ----------------
__global__ void prep_kernel(const float* __restrict__ qkv_w,
                            const float* __restrict__ proj_w,
                            const float* __restrict__ fc1_w,
                            const float* __restrict__ fc2_w,
                            const float* __restrict__ relb,
                            __half* __restrict__ wt, __half* __restrict__ gb) {
    int blk = blockIdx.x;
    int x = threadIdx.x, y = threadIdx.y;
    if (blk >= 768) {
        int h = blk - 768;
        int tid = y * 32 + x;
        #pragma unroll
        for (int it = 0; it < 16; ++it) {
            int e = tid + it * 256;
            int i = e >> 6, j = e & 63;
            int ridx = ((i >> 3) - (j >> 3) + 7) * 15 + ((i & 7) - (j & 7) + 7);
            gb[h * 4096 + e] = __float2half(relb[ridx * 8 + h]);
        }
        return;
    }
    const float* in; __half* out; int R, C, bx, by;
    if (blk < 192)      { in = qkv_w;  out = wt + WT_QKV;  R = DIM; C = QKVC;
                          int i = blk;       bx = (i % 24) * 32; by = (i / 24) * 32; }
    else if (blk < 256) { in = proj_w; out = wt + WT_PROJ; R = DIM; C = DIM;
                          int i = blk - 192; bx = (i % 8) * 32;  by = (i / 8) * 32; }
    else if (blk < 512) { in = fc1_w;  out = wt + WT_FC1;  R = DIM; C = HID;
                          int i = blk - 256; bx = (i % 32) * 32; by = (i / 32) * 32; }
    else                { in = fc2_w;  out = wt + WT_FC2;  R = HID; C = DIM;
                          int i = blk - 512; bx = (i % 8) * 32;  by = (i / 8) * 32; }
    __shared__ float t[32][33];
    #pragma unroll
    for (int j = 0; j < 32; j += 8)
        t[y + j][x] = in[(size_t)(by + y + j) * C + bx + x];
    __syncthreads();
    #pragma unroll
    for (int j = 0; j < 32; j += 8)
        out[(size_t)(bx + y + j) * R + by + x] = __float2half(t[x][y + j]);
}

// ---------------- LayerNorm: one warp per token, fp32 in -> fp16 out ----------
__global__ void ln_kernel(const float* __restrict__ x,
                          const float* __restrict__ g,
                          const float* __restrict__ b,
                          __half* __restrict__ out) {
    int warp = (blockIdx.x * blockDim.x + threadIdx.x) >> 5;
    int lane = threadIdx.x & 31;
    if (warp >= NTOK) return;
    const float* xp = x + (size_t)warp * DIM;
    float4 v0 = *(const float4*)(xp + lane * 4);
    float4 v1 = *(const float4*)(xp + 128 + lane * 4);
    float s  = v0.x + v0.y + v0.z + v0.w + v1.x + v1.y + v1.z + v1.w;
    float ss = v0.x*v0.x + v0.y*v0.y + v0.z*v0.z + v0.w*v0.w
             + v1.x*v1.x + v1.y*v1.y + v1.z*v1.z + v1.w*v1.w;
    #pragma unroll
    for (int o = 16; o > 0; o >>= 1) {
        s  += __shfl_xor_sync(0xffffffffu, s,  o);
        ss += __shfl_xor_sync(0xffffffffu, ss, o);
    }
    float mu  = s * (1.0f / DIM);
    float var = ss * (1.0f / DIM) - mu * mu;
    float inv = rsqrtf(var + 1e-5f);
    float4 g0 = *(const float4*)(g + lane * 4);
    float4 g1 = *(const float4*)(g + 128 + lane * 4);
    float4 b0 = *(const float4*)(b + lane * 4);
    float4 b1 = *(const float4*)(b + 128 + lane * 4);
    __half2 h0 = __floats2half2_rn((v0.x - mu) * inv * g0.x + b0.x,
                                   (v0.y - mu) * inv * g0.y + b0.y);
    __half2 h1 = __floats2half2_rn((v0.z - mu) * inv * g0.z + b0.z,
                                   (v0.w - mu) * inv * g0.w + b0.w);
    __half2 h2 = __floats2half2_rn((v1.x - mu) * inv * g1.x + b1.x,
                                   (v1.y - mu) * inv * g1.y + b1.y);
    __half2 h3 = __floats2half2_rn((v1.z - mu) * inv * g1.z + b1.z,
                                   (v1.w - mu) * inv * g1.w + b1.w);
    __half* op = out + (size_t)warp * DIM;
    ((uint2*)op)[lane]         = make_uint2(*(uint32_t*)&h0, *(uint32_t*)&h1);
    ((uint2*)(op + 128))[lane] = make_uint2(*(uint32_t*)&h2, *(uint32_t*)&h3);
}

// ---------------- fp16 mma.sync GEMM, 128x128 tile, K-chunk 32, 4-stage ring --
#define HSTR 40
#define HSTAGE (128 * HSTR)
#define STG    (2 * HSTAGE)
#define GSM_TOTAL (4 * STG * 2)             // 81920 bytes

template<int EPI, typename OT>
__global__ __launch_bounds__(256, 2)
void tc_gemm(const __half* __restrict__ A, const __half* __restrict__ Bt,
             OT* __restrict__ C, int K, int N,
             const float* __restrict__ bias, const float* __restrict__ res) {
    extern __shared__ __half smh[];
    int tid = threadIdx.x;
    int lane = tid & 31, wid = tid >> 5;
    int warp_m = wid & 3;
    int warp_n = wid >> 2;
    int block_row = blockIdx.y * 128;
    int block_col = blockIdx.x * 128;

    const __half* gA = A  + (size_t)block_row * K;
    const __half* gB = Bt + (size_t)block_col * K;

    auto stage = [&](int c) {
        int s = c & 3;
        int c0 = c * 32;
        uint32_t smA = smem_u32(smh + (size_t)s * STG);
        uint32_t smB = smA + HSTAGE * 2;
        #pragma unroll
        for (int it = 0; it < 2; ++it) {
            int seg = tid + it * 256;
            int r = seg >> 2, sg = (seg & 3) * 8;
            cp_async16(smA + (uint32_t)(r * HSTR + sg) * 2,
                       gA + (size_t)r * K + c0 + sg);
        }
        #pragma unroll
        for (int it = 0; it < 2; ++it) {
            int seg = tid + it * 256;
            int r = seg >> 2, sg = (seg & 3) * 8;
            cp_async16(smB + (uint32_t)(r * HSTR + sg) * 2,
                       gB + (size_t)r * K + c0 + sg);
        }
        asm volatile("cp.async.commit_group;");
    };

    float acc[2][8][4];
    #pragma unroll
    for (int i = 0; i < 2; i++)
        #pragma unroll
        for (int j = 0; j < 8; j++)
            #pragma unroll
            for (int q = 0; q < 4; q++) acc[i][j][q] = 0.0f;

    const int nch = K >> 5;
    stage(0);
    if (nch > 1) stage(1);

    int ldm_row  = lane & 7;
    int ldm_tile = lane >> 3;
    int a_roff = warp_m * 32 + (ldm_tile & 1) * 8 + ldm_row;
    int a_coff = (ldm_tile >> 1) * 8;
    int b_roff = warp_n * 64 + (ldm_tile >> 1) * 8 + ldm_row;
    int b_coff = (ldm_tile & 1) * 8;

    for (int c = 0; c < nch; ++c) {
        if (c + 2 < nch) {
            stage(c + 2);
            asm volatile("cp.async.wait_group 2;");
        } else if (c + 1 < nch) {
            asm volatile("cp.async.wait_group 1;");
        } else {
            asm volatile("cp.async.wait_group 0;");
        }
        __syncthreads();
        int s = c & 3;
        uint32_t As = smem_u32(smh + (size_t)s * STG);
        uint32_t Bs = As + HSTAGE * 2;
        // preload ALL fragments for the chunk (both k16 steps), then MMA burst
        uint32_t a[2][2][4];
        uint32_t b[2][4][4];
        #pragma unroll
        for (int kh = 0; kh < 2; ++kh) {
            int kk = kh * 16;
            #pragma unroll
            for (int am = 0; am < 2; ++am)
                ldm_x4(a[kh][am], As + (uint32_t)((a_roff + am * 16) * HSTR + kk + a_coff) * 2);
            #pragma unroll
            for (int bp = 0; bp < 4; ++bp)
                ldm_x4(b[kh][bp], Bs + (uint32_t)((b_roff + bp * 16) * HSTR + kk + b_coff) * 2);
        }
        #pragma unroll
        for (int kh = 0; kh < 2; ++kh)
            #pragma unroll
            for (int am = 0; am < 2; ++am)
                #pragma unroll
                for (int bp = 0; bp < 4; ++bp) {
                    mma_f16(acc[am][2 * bp],     a[kh][am], b[kh][bp]);
                    mma_f16(acc[am][2 * bp + 1], a[kh][am], b[kh][bp] + 2);
                }
    }

    #pragma unroll
    for (int am = 0; am < 2; ++am) {
        int row0 = block_row + warp_m * 32 + am * 16 + (lane >> 2);
        #pragma unroll
        for (int bn = 0; bn < 8; ++bn) {
            int col = block_col + warp_n * 64 + bn * 8 + 2 * (lane & 3);
            float2 v0 = make_float2(acc[am][bn][0], acc[am][bn][1]);
            float2 v1 = make_float2(acc[am][bn][2], acc[am][bn][3]);
            if (EPI >= 1) {
                float bx = bias[col], by = bias[col + 1];
                v0.x += bx; v0.y += by; v1.x += bx; v1.y += by;
            }
            if (EPI == 2) {
                v0.x = gelu_exact(v0.x); v0.y = gelu_exact(v0.y);
                v1.x = gelu_exact(v1.x); v1.y = gelu_exact(v1.y);
            }
            if (EPI == 3) {
                const float2 r0 = *(const float2*)&res[(size_t)row0 * N + col];
                const float2 r1 = *(const float2*)&res[(size_t)(row0 + 8) * N + col];
                v0.x += r0.x; v0.y += r0.y; v1.x += r1.x; v1.y += r1.y;
            }
            if constexpr (sizeof(OT) == 2) {
                __half2 h0 = __floats2half2_rn(v0.x, v0.y);
                __half2 h1 = __floats2half2_rn(v1.x, v1.y);
                *(__half2*)&C[(size_t)row0 * N + col]       = h0;
                *(__half2*)&C[(size_t)(row0 + 8) * N + col] = h1;
            } else {
                *(float2*)&C[(size_t)row0 * N + col]       = v0;
                *(float2*)&C[(size_t)(row0 + 8) * N + col] = v1;
            }
        }
    }
}

// ---------------- tensor-core windowed attention, 2 windows/block --------------
#define QSTR 40
#define BSTR 72

__global__ __launch_bounds__(256)
void attn_kernel(const __half* __restrict__ qkv,
                 const __half* __restrict__ gbias,
                 __half* __restrict__ out) {
    __shared__ __half sQ[2][64][QSTR];
    __shared__ __half sK[2][64][QSTR];
    __shared__ __half sV[2][64][QSTR];
    __shared__ __half sB[64][BSTR];

    int h  = blockIdx.y;
    int tid = threadIdx.x;
    int lane = tid & 31, w = tid >> 5;
    int widx = w >> 2;
    int wl   = w & 3;

    int wi0 = blockIdx.x * 2;
    int tok_row_arr[2];
    #pragma unroll
    for (int v = 0; v < 2; ++v) {
        int wi = wi0 + v;
        int b = wi >> 6, wrem = wi & 63;
        tok_row_arr[v] = b * 4096 + (wrem >> 3) * 8 * 64 + (wrem & 7) * 8;
    }

    // cp.async staging: Q/K/V straight to SMEM (no register round trip)
    {
        int lv = tid >> 7;
        int t2 = tid & 127;
        int t = t2 >> 1;
        int part = (t2 & 1) * 16;
        int gt = tok_row_arr[lv] + (t >> 3) * 64 + (t & 7);
        const __half* src = qkv + (size_t)gt * QKVC + h * 32 + part;
        cp_async16(smem_u32(&sQ[lv][t][part]),     src);
        cp_async16(smem_u32(&sQ[lv][t][part + 8]), src + 8);
        cp_async16(smem_u32(&sK[lv][t][part]),     src + 256);
        cp_async16(smem_u32(&sK[lv][t][part + 8]), src + 264);
        cp_async16(smem_u32(&sV[lv][t][part]),     src + 512);
        cp_async16(smem_u32(&sV[lv][t][part + 8]), src + 520);
    }
    {
        const __half* gb = gbias + h * 4096;
        #pragma unroll
        for (int it = 0; it < 2; ++it) {
            int i8 = tid + it * 256;
            int r = i8 >> 3, c8 = (i8 & 7) * 8;
            cp_async16(smem_u32(&sB[r][c8]), &gb[r * 64 + c8]);
        }
    }
    asm volatile("cp.async.commit_group;");
    asm volatile("cp.async.wait_group 0;");
    __syncthreads();

    int r0 = wl * 16;
    int quad = lane >> 2, tq = lane & 3;
    int r_lo = r0 + quad;
    int ldm_row = lane & 7;
    int ldm_tile = lane >> 3;

    // ---- S = Q K^T ----
    float sacc[8][4];
    #pragma unroll
    for (int a = 0; a < 8; a++)
        #pragma unroll
        for (int q = 0; q < 4; q++) sacc[a][q] = 0.0f;

    #pragma unroll
    for (int kt = 0; kt < 2; ++kt) {
        int k0 = kt * 16;
        uint32_t af[4];
        ldm_x4(af, smem_u32(&sQ[widx][r0 + (ldm_tile & 1) * 8 + ldm_row]
                               [k0 + (ldm_tile >> 1) * 8]));
        #pragma unroll
        for (int ap = 0; ap < 4; ++ap) {
            int n0 = ap * 16;
            uint32_t bf[4];
            ldm_x4(bf, smem_u32(&sK[widx][n0 + (ldm_tile >> 1) * 8 + ldm_row]
                                   [k0 + (ldm_tile & 1) * 8]));
            mma_f16(sacc[2 * ap],     af, bf);
            mma_f16(sacc[2 * ap + 1], af, bf + 2);
        }
    }

    // ---- scale + bias (ldmatrix fragments) + softmax ----
    const float scale = 0.17677669529663688f;
    float mx_lo = -1e30f, mx_hi = -1e30f;
    #pragma unroll
    for (int j = 0; j < 4; ++j) {
        uint32_t bfr[4];
        ldm_x4(bfr, smem_u32(&sB[r0 + (ldm_tile & 1) * 8 + ldm_row]
                               [16 * j + (ldm_tile >> 1) * 8]));
        float2 b0 = h2f2(bfr[0]);
        float2 b1 = h2f2(bfr[1]);
        float2 b2 = h2f2(bfr[2]);
        float2 b3 = h2f2(bfr[3]);
        int a0 = 2 * j, a1 = 2 * j + 1;
        sacc[a0][0] = fmaf(sacc[a0][0], scale, b0.x);
        sacc[a0][1] = fmaf(sacc[a0][1], scale, b0.y);
        sacc[a0][2] = fmaf(sacc[a0][2], scale, b1.x);
        sacc[a0][3] = fmaf(sacc[a0][3], scale, b1.y);
        sacc[a1][0] = fmaf(sacc[a1][0], scale, b2.x);
        sacc[a1][1] = fmaf(sacc[a1][1], scale, b2.y);
        sacc[a1][2] = fmaf(sacc[a1][2], scale, b3.x);
        sacc[a1][3] = fmaf(sacc[a1][3], scale, b3.y);
    }
    #pragma unroll
    for (int a = 0; a < 8; ++a) {
        mx_lo = fmaxf(mx_lo, fmaxf(sacc[a][0], sacc[a][1]));
        mx_hi = fmaxf(mx_hi, fmaxf(sacc[a][2], sacc[a][3]));
    }
    #pragma unroll
    for (int o = 1; o <= 2; o <<= 1) {
        mx_lo = fmaxf(mx_lo, __shfl_xor_sync(0xffffffffu, mx_lo, o));
        mx_hi = fmaxf(mx_hi, __shfl_xor_sync(0xffffffffu, mx_hi, o));
    }
    float sum_lo = 0.0f, sum_hi = 0.0f;
    #pragma unroll
    for (int a = 0; a < 8; ++a) {
        sacc[a][0] = __expf(sacc[a][0] - mx_lo);
        sacc[a][1] = __expf(sacc[a][1] - mx_lo);
        sacc[a][2] = __expf(sacc[a][2] - mx_hi);
        sacc[a][3] = __expf(sacc[a][3] - mx_hi);
        sum_lo += sacc[a][0] + sacc[a][1];
        sum_hi += sacc[a][2] + sacc[a][3];
    }
    #pragma unroll
    for (int o = 1; o <= 2; o <<= 1) {
        sum_lo += __shfl_xor_sync(0xffffffffu, sum_lo, o);
        sum_hi += __shfl_xor_sync(0xffffffffu, sum_hi, o);
    }

    // ---- O = P V ----
    float oacc[4][4];
    #pragma unroll
    for (int a = 0; a < 4; a++)
        #pragma unroll
        for (int q = 0; q < 4; q++) oacc[a][q] = 0.0f;

    #pragma unroll
    for (int kt = 0; kt < 4; ++kt) {
        uint32_t ap_[4];
        ap_[0] = pack_h2(sacc[2*kt][0],     sacc[2*kt][1]);
        ap_[1] = pack_h2(sacc[2*kt][2],     sacc[2*kt][3]);
        ap_[2] = pack_h2(sacc[2*kt+1][0],   sacc[2*kt+1][1]);
        ap_[3] = pack_h2(sacc[2*kt+1][2],   sacc[2*kt+1][3]);
        int k0 = kt * 16;
        #pragma unroll
        for (int np = 0; np < 2; ++np) {
            int n0 = np * 16;
            uint32_t bf[4];
            ldm_x4_t(bf, smem_u32(&sV[widx][k0 + (ldm_tile & 1) * 8 + ldm_row]
                                     [n0 + (ldm_tile >> 1) * 8]));
            mma_f16(oacc[2 * np],     ap_, bf);
            mma_f16(oacc[2 * np + 1], ap_, bf + 2);
        }
    }

    // ---- normalize + store ----
    float inv_lo = 1.0f / sum_lo, inv_hi = 1.0f / sum_hi;
    int tok_row = tok_row_arr[widx];
    int gt_lo = tok_row + (r_lo >> 3) * 64 + (r_lo & 7);
    int r_hi = r_lo + 8;
    int gt_hi = tok_row + (r_hi >> 3) * 64 + (r_hi & 7);
    #pragma unroll
    for (int a = 0; a < 4; ++a) {
        int col = h * 32 + a * 8 + 2 * tq;
        __half2 lo = __floats2half2_rn(oacc[a][0] * inv_lo, oacc[a][1] * inv_lo);
        __half2 hi = __floats2half2_rn(oacc[a][2] * inv_hi, oacc[a][3] * inv_hi);
        *(__half2*)&out[(size_t)gt_lo * DIM + col] = lo;
        *(__half2*)&out[(size_t)gt_hi * DIM + col] = hi;
    }
}

// ---------------- launch ------------------------------------------------------
extern "C" void kernel_launch(void* const* d_in, const int* in_sizes, int n_in,
                              void* d_out, int out_size) {
    const float* x      = (const float*)d_in[0];
    const float* ln1_g  = (const float*)d_in[3];
    const float* ln1_b  = (const float*)d_in[4];
    const float* qkv_w  = (const float*)d_in[5];
    const float* proj_w = (const float*)d_in[6];
    const float* proj_b = (const float*)d_in[7];
    const float* relb   = (const float*)d_in[8];
    const float* ln2_g  = (const float*)d_in[9];
    const float* ln2_b  = (const float*)d_in[10];
    const float* fc1_w  = (const float*)d_in[11];
    const float* fc1_b  = (const float*)d_in[12];
    const float* fc2_w  = (const float*)d_in[13];
    const float* fc2_b  = (const float*)d_in[14];
    float* out = (float*)d_out;

    __half *p_lnh, *p_qkvh, *p_attnh, *p_mlph, *p_wth, *p_biash;
    cudaGetSymbolAddress((void**)&p_lnh,   g_lnh);
    cudaGetSymbolAddress((void**)&p_qkvh,  g_qkvh);
    cudaGetSymbolAddress((void**)&p_attnh, g_attnh);
    cudaGetSymbolAddress((void**)&p_mlph,  g_mlph);
    cudaGetSymbolAddress((void**)&p_wth,   g_wth);
    cudaGetSymbolAddress((void**)&p_biash, g_biash);

    cudaFuncSetAttribute((const void*)tc_gemm<0, __half>, cudaFuncAttributeMaxDynamicSharedMemorySize, GSM_TOTAL);
    cudaFuncSetAttribute((const void*)tc_gemm<2, __half>, cudaFuncAttributeMaxDynamicSharedMemorySize, GSM_TOTAL);
    cudaFuncSetAttribute((const void*)tc_gemm<3, float >, cudaFuncAttributeMaxDynamicSharedMemorySize, GSM_TOTAL);

    prep_kernel<<<776, dim3(32, 8)>>>(qkv_w, proj_w, fc1_w, fc2_w, relb, p_wth, p_biash);
    ln_kernel<<<NTOK / 8, 256>>>(x, ln1_g, ln1_b, p_lnh);
    tc_gemm<0, __half><<<dim3(QKVC / 128, NTOK / 128), 256, GSM_TOTAL>>>(
        p_lnh, p_wth + WT_QKV, p_qkvh, DIM, QKVC, nullptr, nullptr);
    attn_kernel<<<dim3(512, 8), 256>>>(p_qkvh, p_biash, p_attnh);
    tc_gemm<3, float><<<dim3(DIM / 128, NTOK / 128), 256, GSM_TOTAL>>>(
        p_attnh, p_wth + WT_PROJ, out, DIM, DIM, proj_b, x);
    ln_kernel<<<NTOK / 8, 256>>>(out, ln2_g, ln2_b, p_lnh);
    tc_gemm<2, __half><<<dim3(HID / 128, NTOK / 128), 256, GSM_TOTAL>>>(
        p_lnh, p_wth + WT_FC1, p_mlph, DIM, HID, fc1_b, nullptr);
    tc_gemm<3, float><<<dim3(DIM / 128, NTOK / 128), 256, GSM_TOTAL>>>(
        p_mlph, p_wth + WT_FC2, out, HID, DIM, fc2_b, out);
}